// round 5
// baseline (speedup 1.0000x reference)
#include <cuda_runtime.h>

#define NBANDS 100
#define TT 19
#define FFb 513
#define BB 256
#define KTOT 528          // 400 feat + 128 h
#define GC 512            // combined gate columns: rz(256) | i_n(128) | h_n(128)
#define WINLEN 842
#define FSAMP 16000

// ---------------- device state / scratch ----------------
__device__ float d_fc[NBANDS], d_q0[NBANDS], d_dq[NBANDS];
__device__ float d_Q[BB*NBANDS], d_memL[BB*NBANDS], d_memR[BB*NBANDS];
__device__ __align__(16) float d_A[BB*KTOT];     // [feat(400) | h(128)] per batch row
__device__ __align__(16) float d_Bc[GC*KTOT];    // combined padded weights, [col][k]
__device__ float d_biasc[GC];
__device__ __align__(16) float d_Gp[3*BB*GC];    // split-K partials
__device__ __align__(16) float d_magL[BB*TT*FFb];
__device__ __align__(16) float d_magR[BB*TT*FFb];

// ---------------- constants (ERB scale) ----------------
__global__ void k_consts() {
    int n = threadIdx.x;
    if (n < NBANDS) {
        double E0 = 21.4 * log10(4.37 * 50.0   / 1000.0 + 1.0);
        double E1 = 21.4 * log10(4.37 * 7200.0 / 1000.0 + 1.0);
        double E  = E0 + (E1 - E0) * ((double)n / 99.0);
        double fc = (pow(10.0, E / 21.4) - 1.0) * 1000.0 / 4.37;
        double erb = 24.7 * (4.37 * fc / 1000.0 + 1.0);
        double q0 = fc / (1.019 * erb);
        double En = (E - E0) / (E1 - E0 + 1e-12);
        double dq = 2.0 * (0.5 + 0.5 * En);
        if (dq < 0.001) dq = 0.001;
        d_fc[n] = (float)fc; d_q0[n] = (float)q0; d_dq[n] = (float)dq;
    }
}

__global__ void k_init() {
    int i = blockIdx.x * blockDim.x + threadIdx.x;
    if (i < BB*NBANDS) {
        d_Q[i] = d_q0[i % NBANDS];
        d_memL[i] = 0.f; d_memR[i] = 0.f;
    }
    if (i < BB*128) {
        d_A[(i >> 7) * KTOT + 400 + (i & 127)] = 0.f;   // h = 0
    }
}

// Build combined padded weight matrix + bias
__global__ void k_prep(const float* __restrict__ w_ih, const float* __restrict__ w_hh,
                       const float* __restrict__ b_ih, const float* __restrict__ b_hh) {
    int i = blockIdx.x * blockDim.x + threadIdx.x;
    if (i < GC*KTOT) {
        int col = i / KTOT, k = i - col * KTOT;
        float v;
        if (col < 256)      v = (k < 400) ? w_ih[col*400 + k] : w_hh[col*128 + (k-400)];       // r,z summed
        else if (col < 384) v = (k < 400) ? w_ih[col*400 + k] : 0.f;                            // i_n
        else                v = (k < 400) ? 0.f : w_hh[(col-128)*128 + (k-400)];                // h_n
        d_Bc[col*KTOT + k] = v;
    } else if (i < GC*KTOT + GC) {
        int col = i - GC*KTOT;
        float v;
        if (col < 256)      v = b_ih[col] + b_hh[col];
        else if (col < 384) v = b_ih[col];
        else                v = b_hh[col - 128];
        d_biasc[col] = v;
    }
}

// ---------------- packed L+iR 1024-pt FFT per (b,t) ----------------
// realmode=1: outXL/outXR are real-part planes (B*T*FFb floats each).
// realmode=0: interleaved complex (guarded by out_elems).
__global__ void k_fft(const float* __restrict__ wavL, const float* __restrict__ wavR,
                      float* __restrict__ outXL, float* __restrict__ outXR,
                      int realmode, long long xl_off, long long xr_off, long long out_elems) {
    __shared__ float2 z[1024];
    int bt = blockIdx.x;
    int b = bt / TT, t = bt - b * TT;
    int tid = threadIdx.x;
    const float* wl = wavL + b * FSAMP + t * WINLEN;
    const float* wr = wavR + b * FSAMP + t * WINLEN;

    for (int j = tid; j < 1024; j += 256) {
        float2 v = make_float2(0.f, 0.f);
        if (j < WINLEN) {
            float w = 0.5f - 0.5f * cosf(6.2831853071795864f * (float)j / (float)WINLEN);
            v.x = wl[j] * w; v.y = wr[j] * w;
        }
        z[__brev((unsigned)j) >> 22] = v;
    }
    __syncthreads();

    for (int len = 2; len <= 1024; len <<= 1) {
        int half = len >> 1;
        for (int i = tid; i < 512; i += 256) {
            int j = i & (half - 1);
            int base = ((i - j) << 1) + j;
            float s, c;
            __sincosf(-6.2831853071795864f * (float)j / (float)len, &s, &c);
            float2 u = z[base], v = z[base + half];
            float tr = v.x * c - v.y * s;
            float ti = v.x * s + v.y * c;
            z[base]        = make_float2(u.x + tr, u.y + ti);
            z[base + half] = make_float2(u.x - tr, u.y - ti);
        }
        __syncthreads();
    }

    for (int k = tid; k < FFb; k += 256) {
        float2 zk = z[k];
        float2 zm = z[(1024 - k) & 1023];
        float lr = 0.5f * (zk.x + zm.x), li = 0.5f * (zk.y - zm.y);
        float rr = 0.5f * (zk.y + zm.y), ri = 0.5f * (zm.x - zk.x);
        long long o = (long long)bt * FFb + k;
        if (realmode) {
            outXL[o] = lr;
            outXR[o] = rr;
        } else {
            long long base2 = o * 2;
            if (xl_off + base2 + 1 < out_elems) {
                outXL[base2] = lr; outXL[base2 + 1] = li;
            }
            if (xr_off + base2 + 1 < out_elems) {
                outXR[base2] = rr; outXR[base2 + 1] = ri;
            }
        }
        d_magL[o] = sqrtf(lr * lr + li * li);
        d_magR[o] = sqrtf(rr * rr + ri * ri);
    }
}

// ---------------- per-step: gammatone filterbank (warp per (b,n)) ----------------
__global__ void k_filter(int t, float* __restrict__ outYL, float* __restrict__ outYR,
                         float* __restrict__ outQ) {
    int warp = threadIdx.x >> 5, lane = threadIdx.x & 31;
    int task = blockIdx.x * 8 + warp;
    int b = task / NBANDS, n = task - b * NBANDS;
    float Q  = d_Q[b * NBANDS + n];
    float fc = d_fc[n];
    float bw = fc / (Q + 1e-8f) + 1e-8f;
    float inv = 1.0f / bw;
    float rad = 9.0f * bw;                               // exp(-40.5) cutoff — negligible mass
    int kmin = (int)ceilf((fc - rad) * 0.064f);  if (kmin < 0)   kmin = 0;
    int kmax = (int)floorf((fc + rad) * 0.064f); if (kmax > 512) kmax = 512;

    const float* mL = d_magL + (b * TT + t) * FFb;
    const float* mR = d_magR + (b * TT + t) * FFb;
    float sw = 0.f, sl = 0.f, sr = 0.f;
    for (int k = kmin + lane; k <= kmax; k += 32) {
        float d = ((float)k * 15.625f - fc) * inv;
        float w = __expf(-0.5f * d * d);
        sw += w; sl += w * mL[k]; sr += w * mR[k];
    }
#pragma unroll
    for (int off = 16; off; off >>= 1) {
        sw += __shfl_down_sync(0xffffffffu, sw, off);
        sl += __shfl_down_sync(0xffffffffu, sl, off);
        sr += __shfl_down_sync(0xffffffffu, sr, off);
    }
    if (lane == 0) {
        float den = 1.0f / (sw + 1e-8f);
        float yl = sl * den, yr = sr * den;
        long long oi = ((long long)b * TT + t) * NBANDS + n;
        outYL[oi] = yl; outYR[oi] = yr; outQ[oi] = Q;
        float cL = log1pf(fmaxf(yl, 0.f));
        float cR = log1pf(fmaxf(yr, 0.f));
        int ai = b * KTOT;
        int mi = b * NBANDS + n;
        float mLo = d_memL[mi], mRo = d_memR[mi];
        d_A[ai + n]        = cL;
        d_A[ai + 100 + n]  = mLo;
        d_A[ai + 200 + n]  = cR;
        d_A[ai + 300 + n]  = mRo;
        d_memL[mi] = 0.8f * mLo + 0.2f * cL;
        d_memR[mi] = 0.8f * mRo + 0.2f * cR;
    }
}

// ---------------- per-step: GRU combined GEMM (split-K=3, 32x32 tiles) ----------------
__global__ void __launch_bounds__(128) k_gemm() {
    __shared__ __align__(16) float As[16][36];
    __shared__ __align__(16) float Bs[16][36];
    int col0 = blockIdx.x * 32, row0 = blockIdx.y * 32;
    int kbase = blockIdx.z * 176;
    int tid = threadIdx.x;
    int tx = tid & 7, ty = tid >> 3;        // 8 x 16
    int kk = tid & 15, rr0 = tid >> 4;      // loader mapping
    float acc[2][4];
#pragma unroll
    for (int a = 0; a < 2; a++)
#pragma unroll
        for (int c2 = 0; c2 < 4; c2++) acc[a][c2] = 0.f;

    for (int kt = 0; kt < 176; kt += 16) {
        int kg = kbase + kt + kk;
#pragma unroll
        for (int i = 0; i < 4; i++) {
            int rr = rr0 + i * 8;
            As[kk][rr] = d_A [(row0 + rr) * KTOT + kg];
            Bs[kk][rr] = d_Bc[(col0 + rr) * KTOT + kg];
        }
        __syncthreads();
#pragma unroll
        for (int k2 = 0; k2 < 16; k2++) {
            float2 a  = *(const float2*)&As[k2][ty * 2];
            float4 bq = *(const float4*)&Bs[k2][tx * 4];
            acc[0][0] += a.x * bq.x; acc[0][1] += a.x * bq.y;
            acc[0][2] += a.x * bq.z; acc[0][3] += a.x * bq.w;
            acc[1][0] += a.y * bq.x; acc[1][1] += a.y * bq.y;
            acc[1][2] += a.y * bq.z; acc[1][3] += a.y * bq.w;
        }
        __syncthreads();
    }
    float* g = d_Gp + blockIdx.z * (BB * GC);
#pragma unroll
    for (int a = 0; a < 2; a++) {
        *(float4*)&g[(row0 + ty * 2 + a) * GC + col0 + tx * 4] =
            make_float4(acc[a][0], acc[a][1], acc[a][2], acc[a][3]);
    }
}

// ---------------- per-step: gating + MLP + Q update (row-wise) ----------------
__global__ void __launch_bounds__(256) k_step2(
        const float* __restrict__ w1, const float* __restrict__ b1,
        const float* __restrict__ g1, const float* __restrict__ be1,
        const float* __restrict__ w2, const float* __restrict__ b2,
        const float* __restrict__ g2, const float* __restrict__ be2,
        const float* __restrict__ w3, const float* __restrict__ b3) {
    __shared__ float h_s[4][128];
    __shared__ float a_s[4][128];
    __shared__ float2 wred[8];
    int tid = threadIdx.x;
    int lr = tid >> 6, c = tid & 63;
    int grow = blockIdx.x * 4 + lr;
    int lane = tid & 31, wid = tid >> 5;

    // ---- GRU gating ----
#pragma unroll
    for (int u = 0; u < 2; u++) {
        int d = c + u * 64;
        const float* G0 = d_Gp + grow * GC;
        const float* G1 = d_Gp + (BB + grow) * GC;
        const float* G2 = d_Gp + (2 * BB + grow) * GC;
        float gr  = G0[d]       + G1[d]       + G2[d]       + d_biasc[d];
        float gz  = G0[128 + d] + G1[128 + d] + G2[128 + d] + d_biasc[128 + d];
        float gin = G0[256 + d] + G1[256 + d] + G2[256 + d] + d_biasc[256 + d];
        float ghn = G0[384 + d] + G1[384 + d] + G2[384 + d] + d_biasc[384 + d];
        float rg = 1.f / (1.f + __expf(-gr));
        float zg = 1.f / (1.f + __expf(-gz));
        float ng = tanhf(gin + rg * ghn);
        float hold = d_A[grow * KTOT + 400 + d];
        float hn = (1.f - zg) * ng + zg * hold;
        h_s[lr][d] = hn;
        d_A[grow * KTOT + 400 + d] = hn;
    }
    __syncthreads();

    // ---- two Linear+LN+SiLU layers ----
#pragma unroll 1
    for (int layer = 0; layer < 2; layer++) {
        const float* W  = layer ? w2  : w1;
        const float* Bb = layer ? b2  : b1;
        const float* Gg = layer ? g2  : g1;
        const float* Be = layer ? be2 : be1;
        const float (*in_s)[128] = layer ? (const float(*)[128])a_s : (const float(*)[128])h_s;
        float (*out_s)[128]      = layer ? h_s : a_s;

        float v[2];
#pragma unroll
        for (int u = 0; u < 2; u++) {
            int o = c + u * 64;
            float accv = Bb[o];
            const float* wrow = W + o * 128;
#pragma unroll 8
            for (int k = 0; k < 128; k++) accv += in_s[lr][k] * wrow[k];
            v[u] = accv;
        }
        float s1 = v[0] + v[1], s2 = v[0] * v[0] + v[1] * v[1];
#pragma unroll
        for (int off = 16; off; off >>= 1) {
            s1 += __shfl_down_sync(0xffffffffu, s1, off);
            s2 += __shfl_down_sync(0xffffffffu, s2, off);
        }
        if (lane == 0) wred[wid] = make_float2(s1, s2);
        __syncthreads();
        float2 Ra = wred[lr * 2], Rb = wred[lr * 2 + 1];
        float mean = (Ra.x + Rb.x) * (1.f / 128.f);
        float var  = (Ra.y + Rb.y) * (1.f / 128.f) - mean * mean;
        float invs = rsqrtf(var + 1e-5f);
#pragma unroll
        for (int u = 0; u < 2; u++) {
            int o = c + u * 64;
            float x = (v[u] - mean) * invs * Gg[o] + Be[o];
            float sg = 1.f / (1.f + __expf(-x));
            out_s[lr][o] = x * sg;
        }
        __syncthreads();
    }

    // ---- head + Q update (a2 is in h_s) ----
    if (c < 50) {
#pragma unroll
        for (int u = 0; u < 2; u++) {
            int o = c + u * 50;
            float accv = b3[o];
            const float* wrow = w3 + o * 128;
#pragma unroll 8
            for (int k = 0; k < 128; k++) accv += h_s[lr][k] * wrow[k];
            float delta = tanhf(accv);
            float qt = d_q0[o] + delta * d_dq[o];
            int qi = grow * NBANDS + o;
            float qn = 0.8f * d_Q[qi] + 0.2f * qt;
            qn = fminf(fmaxf(qn, 0.05f), 30.f);
            d_Q[qi] = qn;
        }
    }
}

// ---------------- launch ----------------
extern "C" void kernel_launch(void* const* d_in, const int* in_sizes, int n_in,
                              void* d_out, int out_size) {
    const float* wavL = (const float*)d_in[0];
    const float* wavR = (const float*)d_in[1];
    const float* w_ih = (const float*)d_in[2];
    const float* w_hh = (const float*)d_in[3];
    const float* b_ih = (const float*)d_in[4];
    const float* b_hh = (const float*)d_in[5];
    const float* w1  = (const float*)d_in[6];
    const float* b1  = (const float*)d_in[7];
    const float* g1  = (const float*)d_in[8];
    const float* be1 = (const float*)d_in[9];
    const float* w2  = (const float*)d_in[10];
    const float* b2  = (const float*)d_in[11];
    const float* g2  = (const float*)d_in[12];
    const float* be2 = (const float*)d_in[13];
    const float* w3  = (const float*)d_in[14];
    const float* b3  = (const float*)d_in[15];

    long long out_elems = (long long)out_size;
    const long long NYQ = 3LL * BB * TT * NBANDS;       // 1,459,200
    const long long XSZ = (long long)BB * TT * FFb;     // 2,495,232 (per X output, real plane)
    // realmode: harness flattened complex64 -> float32 (real part only).
    int realmode = (out_elems < NYQ + 3 * XSZ) ? 1 : 0;

    float* out = (float*)d_out;
    float* outYL = out;
    float* outYR = outYL + (long long)BB * TT * NBANDS;
    float* outQ  = outYR + (long long)BB * TT * NBANDS;
    long long xl_off = NYQ;
    long long xr_off = realmode ? (NYQ + XSZ) : (NYQ + 2 * XSZ);
    float* outXL = out + xl_off;
    float* outXR = out + xr_off;

    k_consts<<<1, 128>>>();
    k_init<<<128, 256>>>();
    k_prep<<<(GC * KTOT + GC + 255) / 256, 256>>>(w_ih, w_hh, b_ih, b_hh);
    k_fft<<<BB * TT, 256>>>(wavL, wavR, outXL, outXR, realmode, xl_off, xr_off, out_elems);

    for (int t = 0; t < TT; t++) {
        k_filter<<<BB * NBANDS / 8, 256>>>(t, outYL, outYR, outQ);
        k_gemm<<<dim3(16, 8, 3), 128>>>();
        k_step2<<<64, 256>>>(w1, b1, g1, be1, w2, b2, g2, be2, w3, b3);
    }
}

// round 6
// speedup vs baseline: 3.0068x; 3.0068x over previous
#include <cuda_runtime.h>
#include <cuda_fp16.h>

#define NBANDS 100
#define TT 19
#define FFb 513
#define BB 256
#define KTOT 528          // 400 feat + 128 h
#define GC 512            // combined gate columns: rz(256) | i_n(128) | h_n(128)
#define WINLEN 842
#define FSAMP 16000
#define RPB 2             // batch rows per block
#define NBLK (BB/RPB)     // 128 blocks

// ---------------- device state / scratch ----------------
__device__ float d_fc[NBANDS], d_q0[NBANDS], d_dq[NBANDS];
__device__ __align__(16) __half2 d_W2[KTOT*256];   // [k][colpair], cols (2c,2c+1)
__device__ float d_biasc[GC];
__device__ __align__(16) float d_w1t[128*128];     // [k][o]
__device__ __align__(16) float d_w2t[128*128];
__device__ __align__(16) float d_w3t[128*NBANDS];
__device__ __align__(16) float2 d_mag[BB*TT*FFb];  // (|L|,|R|)

// ---------------- constants (ERB scale) ----------------
__global__ void k_consts() {
    int n = threadIdx.x;
    if (n < NBANDS) {
        double E0 = 21.4 * log10(4.37 * 50.0   / 1000.0 + 1.0);
        double E1 = 21.4 * log10(4.37 * 7200.0 / 1000.0 + 1.0);
        double E  = E0 + (E1 - E0) * ((double)n / 99.0);
        double fc = (pow(10.0, E / 21.4) - 1.0) * 1000.0 / 4.37;
        double erb = 24.7 * (4.37 * fc / 1000.0 + 1.0);
        double q0 = fc / (1.019 * erb);
        double En = (E - E0) / (E1 - E0 + 1e-12);
        double dq = 2.0 * (0.5 + 0.5 * En);
        if (dq < 0.001) dq = 0.001;
        d_fc[n] = (float)fc; d_q0[n] = (float)q0; d_dq[n] = (float)dq;
    }
}

__device__ __forceinline__ float wcomb(const float* w_ih, const float* w_hh, int col, int k) {
    if (col < 256) return (k < 400) ? w_ih[col*400 + k] : w_hh[col*128 + (k-400)];
    if (col < 384) return (k < 400) ? w_ih[col*400 + k] : 0.f;
    return (k < 400) ? 0.f : w_hh[(col-128)*128 + (k-400)];
}

// Build fp16 combined GRU weights, bias, transposed MLP weights
__global__ void k_prep(const float* __restrict__ w_ih, const float* __restrict__ w_hh,
                       const float* __restrict__ b_ih, const float* __restrict__ b_hh,
                       const float* __restrict__ w1, const float* __restrict__ w2,
                       const float* __restrict__ w3) {
    int i = blockIdx.x * blockDim.x + threadIdx.x;
    const int NW2 = KTOT * 256;                 // 135168
    if (i < NW2) {
        int k = i / 256, c = i - k * 256;
        float v0 = wcomb(w_ih, w_hh, 2*c,     k);
        float v1 = wcomb(w_ih, w_hh, 2*c + 1, k);
        d_W2[i] = __floats2half2_rn(v0, v1);
        return;
    }
    int j = i - NW2;
    if (j < GC) {                                // bias
        float v;
        if (j < 256)      v = b_ih[j] + b_hh[j];
        else if (j < 384) v = b_ih[j];
        else              v = b_hh[j - 128];
        d_biasc[j] = v;
        return;
    }
    j -= GC;
    if (j < 128*128) { int k = j >> 7, o = j & 127; d_w1t[k*128 + o] = w1[o*128 + k]; return; }
    j -= 128*128;
    if (j < 128*128) { int k = j >> 7, o = j & 127; d_w2t[k*128 + o] = w2[o*128 + k]; return; }
    j -= 128*128;
    if (j < 128*NBANDS) { int k = j / NBANDS, o = j - k*NBANDS; d_w3t[k*NBANDS + o] = w3[o*128 + k]; }
}

// ---------------- packed L+iR 1024-pt FFT per (b,t) ----------------
__global__ void k_fft(const float* __restrict__ wavL, const float* __restrict__ wavR,
                      float* __restrict__ outXL, float* __restrict__ outXR,
                      int realmode, long long xl_off, long long xr_off, long long out_elems) {
    __shared__ float2 z[1024];
    int bt = blockIdx.x;
    int b = bt / TT, t = bt - b * TT;
    int tid = threadIdx.x;
    const float* wl = wavL + b * FSAMP + t * WINLEN;
    const float* wr = wavR + b * FSAMP + t * WINLEN;

    for (int j = tid; j < 1024; j += 256) {
        float2 v = make_float2(0.f, 0.f);
        if (j < WINLEN) {
            float w = 0.5f - 0.5f * cosf(6.2831853071795864f * (float)j / (float)WINLEN);
            v.x = wl[j] * w; v.y = wr[j] * w;
        }
        z[__brev((unsigned)j) >> 22] = v;
    }
    __syncthreads();

    for (int len = 2; len <= 1024; len <<= 1) {
        int half = len >> 1;
        for (int i = tid; i < 512; i += 256) {
            int j = i & (half - 1);
            int base = ((i - j) << 1) + j;
            float s, c;
            __sincosf(-6.2831853071795864f * (float)j / (float)len, &s, &c);
            float2 u = z[base], v = z[base + half];
            float tr = v.x * c - v.y * s;
            float ti = v.x * s + v.y * c;
            z[base]        = make_float2(u.x + tr, u.y + ti);
            z[base + half] = make_float2(u.x - tr, u.y - ti);
        }
        __syncthreads();
    }

    for (int k = tid; k < FFb; k += 256) {
        float2 zk = z[k];
        float2 zm = z[(1024 - k) & 1023];
        float lr = 0.5f * (zk.x + zm.x), li = 0.5f * (zk.y - zm.y);
        float rr = 0.5f * (zk.y + zm.y), ri = 0.5f * (zm.x - zk.x);
        long long o = (long long)bt * FFb + k;
        if (realmode) {
            outXL[o] = lr;
            outXR[o] = rr;
        } else {
            long long base2 = o * 2;
            if (xl_off + base2 + 1 < out_elems) {
                outXL[base2] = lr; outXL[base2 + 1] = li;
            }
            if (xr_off + base2 + 1 < out_elems) {
                outXR[base2] = rr; outXR[base2 + 1] = ri;
            }
        }
        d_mag[o] = make_float2(sqrtf(lr * lr + li * li), sqrtf(rr * rr + ri * ri));
    }
}

// ---------------- persistent scan: all 19 steps, 2 batch rows per block ----------------
__global__ void __launch_bounds__(512) k_steps(
        float* __restrict__ outYL, float* __restrict__ outYR, float* __restrict__ outQ,
        const float* __restrict__ b1, const float* __restrict__ g1, const float* __restrict__ be1,
        const float* __restrict__ b2, const float* __restrict__ g2, const float* __restrict__ be2,
        const float* __restrict__ b3) {
    __shared__ float2 magc[RPB][FFb];          // 8.2 KB
    __shared__ float a_s[RPB][KTOT];           // feat(400)+h(128), 4.2 KB
    __shared__ float gpart[4][RPB*GC];         // 16 KB split-K partials
    __shared__ float gs[RPB*GC];               // 4 KB reduced gates
    __shared__ float hbuf[RPB][128];
    __shared__ float abuf[RPB][128];
    __shared__ float Qs[RPB][NBANDS];
    __shared__ float memLs[RPB][NBANDS], memRs[RPB][NBANDS];
    __shared__ float2 lnp[RPB][4];

    int tid = threadIdx.x, lane = tid & 31, wid = tid >> 5;
    int b0 = blockIdx.x * RPB;

    // state init
    for (int i = tid; i < RPB*NBANDS; i += 512) {
        int r = i / NBANDS, n = i - r*NBANDS;
        Qs[r][n] = d_q0[n]; memLs[r][n] = 0.f; memRs[r][n] = 0.f;
    }
    for (int i = tid; i < RPB*128; i += 512) a_s[i >> 7][400 + (i & 127)] = 0.f;
    __syncthreads();

    for (int t = 0; t < TT; t++) {
        // ---- load magnitude rows ----
        for (int i = tid; i < RPB*FFb; i += 512) {
            int r = i / FFb, k = i - r*FFb;
            magc[r][k] = d_mag[(long long)((b0 + r)*TT + t)*FFb + k];
        }
        __syncthreads();

        // ---- gammatone filterbank: warp per (row,band) ----
        for (int task = wid; task < RPB*NBANDS; task += 16) {
            int r = task / NBANDS, n = task - r*NBANDS;
            float Q  = Qs[r][n];
            float fc = d_fc[n];
            float bw = fc / (Q + 1e-8f) + 1e-8f;
            float inv = 1.0f / bw;
            float rad = 5.0f * bw;                       // exp(-12.5) tail, ~1e-6 rel
            int kmin = (int)ceilf((fc - rad) * 0.064f);  if (kmin < 0)   kmin = 0;
            int kmax = (int)floorf((fc + rad) * 0.064f); if (kmax > 512) kmax = 512;
            float sw = 0.f, sl = 0.f, sr = 0.f;
            for (int k = kmin + lane; k <= kmax; k += 32) {
                float d = ((float)k * 15.625f - fc) * inv;
                float w = __expf(-0.5f * d * d);
                float2 m = magc[r][k];
                sw += w; sl += w * m.x; sr += w * m.y;
            }
#pragma unroll
            for (int off = 16; off; off >>= 1) {
                sw += __shfl_down_sync(0xffffffffu, sw, off);
                sl += __shfl_down_sync(0xffffffffu, sl, off);
                sr += __shfl_down_sync(0xffffffffu, sr, off);
            }
            if (lane == 0) {
                float den = 1.0f / (sw + 1e-8f);
                float yl = sl * den, yr = sr * den;
                long long oi = ((long long)(b0 + r)*TT + t)*NBANDS + n;
                outYL[oi] = yl; outYR[oi] = yr; outQ[oi] = Q;
                float cL = log1pf(fmaxf(yl, 0.f));
                float cR = log1pf(fmaxf(yr, 0.f));
                float mLo = memLs[r][n], mRo = memRs[r][n];
                a_s[r][n]       = cL;
                a_s[r][100 + n] = mLo;
                a_s[r][200 + n] = cR;
                a_s[r][300 + n] = mRo;
                memLs[r][n] = 0.8f * mLo + 0.2f * cL;
                memRs[r][n] = 0.8f * mRo + 0.2f * cR;
            }
        }
        __syncthreads();

        // ---- GRU GEMM: warp = (row, colhalf, k-quarter), lane = 8 columns ----
        {
            int row = wid >> 3, sub = wid & 7, ch = sub >> 2, kq = sub & 3;
            int c0 = ch * 128 + lane * 4;                // half2 index
            float acc[8];
#pragma unroll
            for (int j = 0; j < 8; j++) acc[j] = 0.f;
            int k0 = kq * 132;
#pragma unroll 4
            for (int k = k0; k < k0 + 132; k++) {
                float av = a_s[row][k];
                uint4 w4 = *(const uint4*)&d_W2[k*256 + c0];
                float2 f0 = __half22float2(*(__half2*)&w4.x);
                float2 f1 = __half22float2(*(__half2*)&w4.y);
                float2 f2 = __half22float2(*(__half2*)&w4.z);
                float2 f3 = __half22float2(*(__half2*)&w4.w);
                acc[0] += av * f0.x; acc[1] += av * f0.y;
                acc[2] += av * f1.x; acc[3] += av * f1.y;
                acc[4] += av * f2.x; acc[5] += av * f2.y;
                acc[6] += av * f3.x; acc[7] += av * f3.y;
            }
            float* gp = &gpart[kq][row*GC + ch*256 + lane*8];
            *(float4*)gp       = make_float4(acc[0], acc[1], acc[2], acc[3]);
            *(float4*)(gp + 4) = make_float4(acc[4], acc[5], acc[6], acc[7]);
        }
        __syncthreads();

        // ---- reduce split-K + bias ----
        for (int i = tid; i < RPB*GC; i += 512) {
            int col = i & (GC - 1);
            gs[i] = d_biasc[col] + gpart[0][i] + gpart[1][i] + gpart[2][i] + gpart[3][i];
        }
        __syncthreads();

        // ---- GRU gating ----
        if (tid < RPB*128) {
            int row = tid >> 7, d = tid & 127;
            const float* g = &gs[row*GC];
            float gr = g[d], gz = g[128 + d], gin = g[256 + d], ghn = g[384 + d];
            float rg = 1.f / (1.f + __expf(-gr));
            float zg = 1.f / (1.f + __expf(-gz));
            float ng = tanhf(gin + rg * ghn);
            float hold = a_s[row][400 + d];
            float hn = (1.f - zg) * ng + zg * hold;
            a_s[row][400 + d] = hn;
            hbuf[row][d] = hn;
        }
        __syncthreads();

        // ---- MLP layer 1 (Linear + LN + SiLU) ----
        float v1 = 0.f;
        if (tid < RPB*128) {
            int row = tid >> 7, o = tid & 127;
            float acc = b1[o];
#pragma unroll 8
            for (int k = 0; k < 128; k++) acc += hbuf[row][k] * d_w1t[k*128 + o];
            v1 = acc;
            float s1 = acc, s2 = acc * acc;
#pragma unroll
            for (int off = 16; off; off >>= 1) {
                s1 += __shfl_down_sync(0xffffffffu, s1, off);
                s2 += __shfl_down_sync(0xffffffffu, s2, off);
            }
            if (lane == 0) lnp[row][wid & 3] = make_float2(s1, s2);
        }
        __syncthreads();
        if (tid < RPB*128) {
            int row = tid >> 7, o = tid & 127;
            float S1 = 0.f, S2 = 0.f;
#pragma unroll
            for (int j = 0; j < 4; j++) { S1 += lnp[row][j].x; S2 += lnp[row][j].y; }
            float mean = S1 * (1.f/128.f);
            float var  = S2 * (1.f/128.f) - mean * mean;
            float isd  = rsqrtf(var + 1e-5f);
            float x = (v1 - mean) * isd * g1[o] + be1[o];
            abuf[row][o] = x / (1.f + __expf(-x));
        }
        __syncthreads();

        // ---- MLP layer 2 ----
        float v2 = 0.f;
        if (tid < RPB*128) {
            int row = tid >> 7, o = tid & 127;
            float acc = b2[o];
#pragma unroll 8
            for (int k = 0; k < 128; k++) acc += abuf[row][k] * d_w2t[k*128 + o];
            v2 = acc;
            float s1 = acc, s2 = acc * acc;
#pragma unroll
            for (int off = 16; off; off >>= 1) {
                s1 += __shfl_down_sync(0xffffffffu, s1, off);
                s2 += __shfl_down_sync(0xffffffffu, s2, off);
            }
            if (lane == 0) lnp[row][wid & 3] = make_float2(s1, s2);
        }
        __syncthreads();
        if (tid < RPB*128) {
            int row = tid >> 7, o = tid & 127;
            float S1 = 0.f, S2 = 0.f;
#pragma unroll
            for (int j = 0; j < 4; j++) { S1 += lnp[row][j].x; S2 += lnp[row][j].y; }
            float mean = S1 * (1.f/128.f);
            float var  = S2 * (1.f/128.f) - mean * mean;
            float isd  = rsqrtf(var + 1e-5f);
            float x = (v2 - mean) * isd * g2[o] + be2[o];
            hbuf[row][o] = x / (1.f + __expf(-x));   // h no longer needed in hbuf (saved in a_s)
        }
        __syncthreads();

        // ---- head + Q update ----
        if (tid < RPB*NBANDS) {
            int row = tid / NBANDS, o = tid - row*NBANDS;
            float acc = b3[o];
#pragma unroll 8
            for (int k = 0; k < 128; k++) acc += hbuf[row][k] * d_w3t[k*NBANDS + o];
            float delta = tanhf(acc);
            float qt = d_q0[o] + delta * d_dq[o];
            float qn = 0.8f * Qs[row][o] + 0.2f * qt;
            Qs[row][o] = fminf(fmaxf(qn, 0.05f), 30.f);
        }
        __syncthreads();
    }
}

// ---------------- launch ----------------
extern "C" void kernel_launch(void* const* d_in, const int* in_sizes, int n_in,
                              void* d_out, int out_size) {
    const float* wavL = (const float*)d_in[0];
    const float* wavR = (const float*)d_in[1];
    const float* w_ih = (const float*)d_in[2];
    const float* w_hh = (const float*)d_in[3];
    const float* b_ih = (const float*)d_in[4];
    const float* b_hh = (const float*)d_in[5];
    const float* w1  = (const float*)d_in[6];
    const float* b1  = (const float*)d_in[7];
    const float* g1  = (const float*)d_in[8];
    const float* be1 = (const float*)d_in[9];
    const float* w2  = (const float*)d_in[10];
    const float* b2  = (const float*)d_in[11];
    const float* g2  = (const float*)d_in[12];
    const float* be2 = (const float*)d_in[13];
    const float* w3  = (const float*)d_in[14];
    const float* b3  = (const float*)d_in[15];

    long long out_elems = (long long)out_size;
    const long long NYQ = 3LL * BB * TT * NBANDS;       // 1,459,200
    const long long XSZ = (long long)BB * TT * FFb;     // 2,495,232 per X (real plane)
    int realmode = (out_elems < NYQ + 3 * XSZ) ? 1 : 0;

    float* out = (float*)d_out;
    float* outYL = out;
    float* outYR = outYL + (long long)BB * TT * NBANDS;
    float* outQ  = outYR + (long long)BB * TT * NBANDS;
    long long xl_off = NYQ;
    long long xr_off = realmode ? (NYQ + XSZ) : (NYQ + 2 * XSZ);
    float* outXL = out + xl_off;
    float* outXR = out + xr_off;

    const int PREP_N = KTOT*256 + GC + 128*128 + 128*128 + 128*NBANDS;
    k_consts<<<1, 128>>>();
    k_prep<<<(PREP_N + 255) / 256, 256>>>(w_ih, w_hh, b_ih, b_hh, w1, w2, w3);
    k_fft<<<BB * TT, 256>>>(wavL, wavR, outXL, outXR, realmode, xl_off, xr_off, out_elems);
    k_steps<<<NBLK, 512>>>(outYL, outYR, outQ, b1, g1, be1, b2, g2, be2, b3);
}

// round 7
// speedup vs baseline: 3.5816x; 1.1912x over previous
#include <cuda_runtime.h>
#include <cuda_fp16.h>

#define NBANDS 100
#define TT 19
#define FFb 513
#define BB 256
#define KTOT 528          // 400 feat + 128 h
#define GC 512            // combined gate columns: rz(256) | i_n(128) | h_n(128)
#define WINLEN 842
#define FSAMP 16000
#define RPB 2             // batch rows per block
#define NBLK (BB/RPB)     // 128 blocks
#define NTHR 1024
#define KSPLIT 8          // split-K ways (66 k each)

// ---------------- device state / scratch ----------------
__device__ float d_fc[NBANDS], d_q0[NBANDS], d_dq[NBANDS];
__device__ __align__(16) __half2 d_W2[KTOT*256];   // [k][colpair], cols (2c,2c+1)
__device__ float d_biasc[GC];
__device__ __align__(16) float d_w1t[128*128];     // [k][o]
__device__ __align__(16) float d_w2t[128*128];
__device__ __align__(16) float d_w3t[128*NBANDS];
__device__ __align__(16) float2 d_mag[BB*TT*FFb];  // (|L|,|R|)

// ---------------- constants (ERB scale) ----------------
__global__ void k_consts() {
    int n = threadIdx.x;
    if (n < NBANDS) {
        double E0 = 21.4 * log10(4.37 * 50.0   / 1000.0 + 1.0);
        double E1 = 21.4 * log10(4.37 * 7200.0 / 1000.0 + 1.0);
        double E  = E0 + (E1 - E0) * ((double)n / 99.0);
        double fc = (pow(10.0, E / 21.4) - 1.0) * 1000.0 / 4.37;
        double erb = 24.7 * (4.37 * fc / 1000.0 + 1.0);
        double q0 = fc / (1.019 * erb);
        double En = (E - E0) / (E1 - E0 + 1e-12);
        double dq = 2.0 * (0.5 + 0.5 * En);
        if (dq < 0.001) dq = 0.001;
        d_fc[n] = (float)fc; d_q0[n] = (float)q0; d_dq[n] = (float)dq;
    }
}

__device__ __forceinline__ float wcomb(const float* w_ih, const float* w_hh, int col, int k) {
    if (col < 256) return (k < 400) ? w_ih[col*400 + k] : w_hh[col*128 + (k-400)];
    if (col < 384) return (k < 400) ? w_ih[col*400 + k] : 0.f;
    return (k < 400) ? 0.f : w_hh[(col-128)*128 + (k-400)];
}

// Build fp16 combined GRU weights, bias, transposed MLP weights
__global__ void k_prep(const float* __restrict__ w_ih, const float* __restrict__ w_hh,
                       const float* __restrict__ b_ih, const float* __restrict__ b_hh,
                       const float* __restrict__ w1, const float* __restrict__ w2,
                       const float* __restrict__ w3) {
    int i = blockIdx.x * blockDim.x + threadIdx.x;
    const int NW2 = KTOT * 256;                 // 135168
    if (i < NW2) {
        int k = i / 256, c = i - k * 256;
        float v0 = wcomb(w_ih, w_hh, 2*c,     k);
        float v1 = wcomb(w_ih, w_hh, 2*c + 1, k);
        d_W2[i] = __floats2half2_rn(v0, v1);
        return;
    }
    int j = i - NW2;
    if (j < GC) {                                // bias
        float v;
        if (j < 256)      v = b_ih[j] + b_hh[j];
        else if (j < 384) v = b_ih[j];
        else              v = b_hh[j - 128];
        d_biasc[j] = v;
        return;
    }
    j -= GC;
    if (j < 128*128) { int k = j >> 7, o = j & 127; d_w1t[k*128 + o] = w1[o*128 + k]; return; }
    j -= 128*128;
    if (j < 128*128) { int k = j >> 7, o = j & 127; d_w2t[k*128 + o] = w2[o*128 + k]; return; }
    j -= 128*128;
    if (j < 128*NBANDS) { int k = j / NBANDS, o = j - k*NBANDS; d_w3t[k*NBANDS + o] = w3[o*128 + k]; }
}

// ---------------- packed L+iR 1024-pt FFT per (b,t) ----------------
__global__ void k_fft(const float* __restrict__ wavL, const float* __restrict__ wavR,
                      float* __restrict__ outXL, float* __restrict__ outXR,
                      int realmode, long long xl_off, long long xr_off, long long out_elems) {
    __shared__ float2 z[1024];
    int bt = blockIdx.x;
    int b = bt / TT, t = bt - b * TT;
    int tid = threadIdx.x;
    const float* wl = wavL + b * FSAMP + t * WINLEN;
    const float* wr = wavR + b * FSAMP + t * WINLEN;

    for (int j = tid; j < 1024; j += 256) {
        float2 v = make_float2(0.f, 0.f);
        if (j < WINLEN) {
            float w = 0.5f - 0.5f * cosf(6.2831853071795864f * (float)j / (float)WINLEN);
            v.x = wl[j] * w; v.y = wr[j] * w;
        }
        z[__brev((unsigned)j) >> 22] = v;
    }
    __syncthreads();

    for (int len = 2; len <= 1024; len <<= 1) {
        int half = len >> 1;
        for (int i = tid; i < 512; i += 256) {
            int j = i & (half - 1);
            int base = ((i - j) << 1) + j;
            float s, c;
            __sincosf(-6.2831853071795864f * (float)j / (float)len, &s, &c);
            float2 u = z[base], v = z[base + half];
            float tr = v.x * c - v.y * s;
            float ti = v.x * s + v.y * c;
            z[base]        = make_float2(u.x + tr, u.y + ti);
            z[base + half] = make_float2(u.x - tr, u.y - ti);
        }
        __syncthreads();
    }

    for (int k = tid; k < FFb; k += 256) {
        float2 zk = z[k];
        float2 zm = z[(1024 - k) & 1023];
        float lr = 0.5f * (zk.x + zm.x), li = 0.5f * (zk.y - zm.y);
        float rr = 0.5f * (zk.y + zm.y), ri = 0.5f * (zm.x - zk.x);
        long long o = (long long)bt * FFb + k;
        if (realmode) {
            outXL[o] = lr;
            outXR[o] = rr;
        } else {
            long long base2 = o * 2;
            if (xl_off + base2 + 1 < out_elems) {
                outXL[base2] = lr; outXL[base2 + 1] = li;
            }
            if (xr_off + base2 + 1 < out_elems) {
                outXR[base2] = rr; outXR[base2 + 1] = ri;
            }
        }
        d_mag[o] = make_float2(sqrtf(lr * lr + li * li), sqrtf(rr * rr + ri * ri));
    }
}

// ---------------- persistent scan: all 19 steps, 2 batch rows per block ----------------
__global__ void __launch_bounds__(NTHR) k_steps(
        float* __restrict__ outYL, float* __restrict__ outYR, float* __restrict__ outQ,
        const float* __restrict__ b1, const float* __restrict__ g1, const float* __restrict__ be1,
        const float* __restrict__ b2, const float* __restrict__ g2, const float* __restrict__ be2,
        const float* __restrict__ b3) {
    // magc (filter phase) and gpart (GEMM phase) are temporally disjoint within a
    // step (filter reads magc, __syncthreads, GEMM writes gpart); alias them.
    __shared__ __align__(16) float u_smem[KSPLIT * RPB * GC];       // 32 KB
    float2 (*magc)[FFb]   = (float2 (*)[FFb])u_smem;                 // [RPB][FFb]
    float  (*gpart)[RPB*GC] = (float (*)[RPB*GC])u_smem;             // [KSPLIT][RPB*GC]
    __shared__ float a_s[RPB][KTOT];           // feat(400)+h(128)
    __shared__ float gs[RPB*GC];               // reduced gates
    __shared__ float hbuf[RPB][128];
    __shared__ float abuf[RPB][128];
    __shared__ float Qs[RPB][NBANDS];
    __shared__ float memLs[RPB][NBANDS], memRs[RPB][NBANDS];
    __shared__ float2 lnp[RPB][4];

    int tid = threadIdx.x, lane = tid & 31, wid = tid >> 5;
    int b0 = blockIdx.x * RPB;

    // state init
    for (int i = tid; i < RPB*NBANDS; i += NTHR) {
        int r = i / NBANDS, n = i - r*NBANDS;
        Qs[r][n] = d_q0[n]; memLs[r][n] = 0.f; memRs[r][n] = 0.f;
    }
    for (int i = tid; i < RPB*128; i += NTHR) a_s[i >> 7][400 + (i & 127)] = 0.f;
    __syncthreads();

    for (int t = 0; t < TT; t++) {
        // ---- load magnitude rows ----
        for (int i = tid; i < RPB*FFb; i += NTHR) {
            int r = i / FFb, k = i - r*FFb;
            magc[r][k] = d_mag[(long long)((b0 + r)*TT + t)*FFb + k];
        }
        __syncthreads();

        // ---- gammatone filterbank: warp per (row,band) ----
        for (int task = wid; task < RPB*NBANDS; task += 32) {
            int r = task / NBANDS, n = task - r*NBANDS;
            float Q  = Qs[r][n];
            float fc = d_fc[n];
            float bw = fc / (Q + 1e-8f) + 1e-8f;
            float inv = 1.0f / bw;
            float rad = 5.0f * bw;                       // exp(-12.5) tail, ~1e-6 rel
            int kmin = (int)ceilf((fc - rad) * 0.064f);  if (kmin < 0)   kmin = 0;
            int kmax = (int)floorf((fc + rad) * 0.064f); if (kmax > 512) kmax = 512;
            float sw = 0.f, sl = 0.f, sr = 0.f;
            for (int k = kmin + lane; k <= kmax; k += 32) {
                float d = ((float)k * 15.625f - fc) * inv;
                float w = __expf(-0.5f * d * d);
                float2 m = magc[r][k];
                sw += w; sl += w * m.x; sr += w * m.y;
            }
#pragma unroll
            for (int off = 16; off; off >>= 1) {
                sw += __shfl_down_sync(0xffffffffu, sw, off);
                sl += __shfl_down_sync(0xffffffffu, sl, off);
                sr += __shfl_down_sync(0xffffffffu, sr, off);
            }
            if (lane == 0) {
                float den = 1.0f / (sw + 1e-8f);
                float yl = sl * den, yr = sr * den;
                long long oi = ((long long)(b0 + r)*TT + t)*NBANDS + n;
                outYL[oi] = yl; outYR[oi] = yr; outQ[oi] = Q;
                float cL = log1pf(fmaxf(yl, 0.f));
                float cR = log1pf(fmaxf(yr, 0.f));
                float mLo = memLs[r][n], mRo = memRs[r][n];
                a_s[r][n]       = cL;
                a_s[r][100 + n] = mLo;
                a_s[r][200 + n] = cR;
                a_s[r][300 + n] = mRo;
                memLs[r][n] = 0.8f * mLo + 0.2f * cL;
                memRs[r][n] = 0.8f * mRo + 0.2f * cR;
            }
        }
        __syncthreads();   // filter done reading magc; gpart may now clobber it

        // ---- GRU GEMM: warp = (row, colhalf, k-eighth), lane = 8 columns ----
        {
            int row = wid >> 4, ch = (wid >> 3) & 1, kq = wid & 7;
            int c0 = ch * 128 + lane * 4;                // half2 index
            float acc[8];
#pragma unroll
            for (int j = 0; j < 8; j++) acc[j] = 0.f;
            int k0 = kq * 66;
#pragma unroll 6
            for (int k = k0; k < k0 + 66; k++) {
                float av = a_s[row][k];
                uint4 w4 = *(const uint4*)&d_W2[k*256 + c0];
                float2 f0 = __half22float2(*(__half2*)&w4.x);
                float2 f1 = __half22float2(*(__half2*)&w4.y);
                float2 f2 = __half22float2(*(__half2*)&w4.z);
                float2 f3 = __half22float2(*(__half2*)&w4.w);
                acc[0] += av * f0.x; acc[1] += av * f0.y;
                acc[2] += av * f1.x; acc[3] += av * f1.y;
                acc[4] += av * f2.x; acc[5] += av * f2.y;
                acc[6] += av * f3.x; acc[7] += av * f3.y;
            }
            float* gp = &gpart[kq][row*GC + ch*256 + lane*8];
            *(float4*)gp       = make_float4(acc[0], acc[1], acc[2], acc[3]);
            *(float4*)(gp + 4) = make_float4(acc[4], acc[5], acc[6], acc[7]);
        }
        __syncthreads();

        // ---- reduce split-K + bias (one thread per gate element) ----
        if (tid < RPB*GC) {
            int col = tid & (GC - 1);
            float s = d_biasc[col];
#pragma unroll
            for (int q = 0; q < KSPLIT; q++) s += gpart[q][tid];
            gs[tid] = s;
        }
        __syncthreads();

        // ---- GRU gating ----
        if (tid < RPB*128) {
            int row = tid >> 7, d = tid & 127;
            const float* g = &gs[row*GC];
            float gr = g[d], gz = g[128 + d], gin = g[256 + d], ghn = g[384 + d];
            float rg = 1.f / (1.f + __expf(-gr));
            float zg = 1.f / (1.f + __expf(-gz));
            float ng = tanhf(gin + rg * ghn);
            float hold = a_s[row][400 + d];
            float hn = (1.f - zg) * ng + zg * hold;
            a_s[row][400 + d] = hn;
            hbuf[row][d] = hn;
        }
        __syncthreads();

        // ---- MLP layer 1 (Linear + LN + SiLU) ----
        float v1 = 0.f;
        if (tid < RPB*128) {
            int row = tid >> 7, o = tid & 127;
            float acc = b1[o];
#pragma unroll 8
            for (int k = 0; k < 128; k++) acc += hbuf[row][k] * d_w1t[k*128 + o];
            v1 = acc;
            float s1 = acc, s2 = acc * acc;
#pragma unroll
            for (int off = 16; off; off >>= 1) {
                s1 += __shfl_down_sync(0xffffffffu, s1, off);
                s2 += __shfl_down_sync(0xffffffffu, s2, off);
            }
            if (lane == 0) lnp[row][wid & 3] = make_float2(s1, s2);
        }
        __syncthreads();
        if (tid < RPB*128) {
            int row = tid >> 7, o = tid & 127;
            float S1 = 0.f, S2 = 0.f;
#pragma unroll
            for (int j = 0; j < 4; j++) { S1 += lnp[row][j].x; S2 += lnp[row][j].y; }
            float mean = S1 * (1.f/128.f);
            float var  = S2 * (1.f/128.f) - mean * mean;
            float isd  = rsqrtf(var + 1e-5f);
            float x = (v1 - mean) * isd * g1[o] + be1[o];
            abuf[row][o] = x / (1.f + __expf(-x));
        }
        __syncthreads();

        // ---- MLP layer 2 ----
        float v2 = 0.f;
        if (tid < RPB*128) {
            int row = tid >> 7, o = tid & 127;
            float acc = b2[o];
#pragma unroll 8
            for (int k = 0; k < 128; k++) acc += abuf[row][k] * d_w2t[k*128 + o];
            v2 = acc;
            float s1 = acc, s2 = acc * acc;
#pragma unroll
            for (int off = 16; off; off >>= 1) {
                s1 += __shfl_down_sync(0xffffffffu, s1, off);
                s2 += __shfl_down_sync(0xffffffffu, s2, off);
            }
            if (lane == 0) lnp[row][wid & 3] = make_float2(s1, s2);
        }
        __syncthreads();
        if (tid < RPB*128) {
            int row = tid >> 7, o = tid & 127;
            float S1 = 0.f, S2 = 0.f;
#pragma unroll
            for (int j = 0; j < 4; j++) { S1 += lnp[row][j].x; S2 += lnp[row][j].y; }
            float mean = S1 * (1.f/128.f);
            float var  = S2 * (1.f/128.f) - mean * mean;
            float isd  = rsqrtf(var + 1e-5f);
            float x = (v2 - mean) * isd * g2[o] + be2[o];
            hbuf[row][o] = x / (1.f + __expf(-x));
        }
        __syncthreads();

        // ---- head + Q update ----
        if (tid < RPB*NBANDS) {
            int row = tid / NBANDS, o = tid - row*NBANDS;
            float acc = b3[o];
#pragma unroll 8
            for (int k = 0; k < 128; k++) acc += hbuf[row][k] * d_w3t[k*NBANDS + o];
            float delta = tanhf(acc);
            float qt = d_q0[o] + delta * d_dq[o];
            float qn = 0.8f * Qs[row][o] + 0.2f * qt;
            Qs[row][o] = fminf(fmaxf(qn, 0.05f), 30.f);
        }
        __syncthreads();
    }
}

// ---------------- launch ----------------
extern "C" void kernel_launch(void* const* d_in, const int* in_sizes, int n_in,
                              void* d_out, int out_size) {
    const float* wavL = (const float*)d_in[0];
    const float* wavR = (const float*)d_in[1];
    const float* w_ih = (const float*)d_in[2];
    const float* w_hh = (const float*)d_in[3];
    const float* b_ih = (const float*)d_in[4];
    const float* b_hh = (const float*)d_in[5];
    const float* w1  = (const float*)d_in[6];
    const float* b1  = (const float*)d_in[7];
    const float* g1  = (const float*)d_in[8];
    const float* be1 = (const float*)d_in[9];
    const float* w2  = (const float*)d_in[10];
    const float* b2  = (const float*)d_in[11];
    const float* g2  = (const float*)d_in[12];
    const float* be2 = (const float*)d_in[13];
    const float* w3  = (const float*)d_in[14];
    const float* b3  = (const float*)d_in[15];

    long long out_elems = (long long)out_size;
    const long long NYQ = 3LL * BB * TT * NBANDS;       // 1,459,200
    const long long XSZ = (long long)BB * TT * FFb;     // 2,495,232 per X (real plane)
    int realmode = (out_elems < NYQ + 3 * XSZ) ? 1 : 0;

    float* out = (float*)d_out;
    float* outYL = out;
    float* outYR = outYL + (long long)BB * TT * NBANDS;
    float* outQ  = outYR + (long long)BB * TT * NBANDS;
    long long xl_off = NYQ;
    long long xr_off = realmode ? (NYQ + XSZ) : (NYQ + 2 * XSZ);
    float* outXL = out + xl_off;
    float* outXR = out + xr_off;

    const int PREP_N = KTOT*256 + GC + 128*128 + 128*128 + 128*NBANDS;
    k_consts<<<1, 128>>>();
    k_prep<<<(PREP_N + 255) / 256, 256>>>(w_ih, w_hh, b_ih, b_hh, w1, w2, w3);
    k_fft<<<BB * TT, 256>>>(wavL, wavR, outXL, outXR, realmode, xl_off, xr_off, out_elems);
    k_steps<<<NBLK, NTHR>>>(outYL, outYR, outQ, b1, g1, be1, b2, g2, be2, b3);
}

// round 8
// speedup vs baseline: 4.4990x; 1.2561x over previous
#include <cuda_runtime.h>
#include <cuda_fp16.h>

#define NBANDS 100
#define TT 19
#define FFb 513
#define BB 256
#define KTOT 528          // 400 feat + 128 h
#define GC 512            // combined gate columns: rz(256) | i_n(128) | h_n(128)
#define WINLEN 842
#define FSAMP 16000
#define RPB 2             // batch rows per block
#define NBLK (BB/RPB)     // 128 blocks
#define NTHR 1024
#define KSPLIT 16         // split-K ways (33 k each)
#define DYN_SMEM (KSPLIT*RPB*GC*4)   // 64 KB fp32 partials (aliases mag cache)

// ---------------- device state / scratch ----------------
__device__ float d_fc[NBANDS], d_q0[NBANDS], d_dq[NBANDS];
__device__ __align__(16) __half2 d_W2[KTOT*256];   // [k][colpair], cols (2c,2c+1)
__device__ float d_biasc[GC];
__device__ __align__(16) float d_w1t[128*128];     // [k][o]
__device__ __align__(16) float d_w2t[128*128];
__device__ __align__(16) float d_w3t[128*NBANDS];
__device__ __align__(16) float2 d_mag[BB*TT*FFb];  // (|L|,|R|)

// ---------------- constants (ERB scale) ----------------
__global__ void k_consts() {
    int n = threadIdx.x;
    if (n < NBANDS) {
        double E0 = 21.4 * log10(4.37 * 50.0   / 1000.0 + 1.0);
        double E1 = 21.4 * log10(4.37 * 7200.0 / 1000.0 + 1.0);
        double E  = E0 + (E1 - E0) * ((double)n / 99.0);
        double fc = (pow(10.0, E / 21.4) - 1.0) * 1000.0 / 4.37;
        double erb = 24.7 * (4.37 * fc / 1000.0 + 1.0);
        double q0 = fc / (1.019 * erb);
        double En = (E - E0) / (E1 - E0 + 1e-12);
        double dq = 2.0 * (0.5 + 0.5 * En);
        if (dq < 0.001) dq = 0.001;
        d_fc[n] = (float)fc; d_q0[n] = (float)q0; d_dq[n] = (float)dq;
    }
}

__device__ __forceinline__ float wcomb(const float* w_ih, const float* w_hh, int col, int k) {
    if (col < 256) return (k < 400) ? w_ih[col*400 + k] : w_hh[col*128 + (k-400)];
    if (col < 384) return (k < 400) ? w_ih[col*400 + k] : 0.f;
    return (k < 400) ? 0.f : w_hh[(col-128)*128 + (k-400)];
}

// Build fp16 combined GRU weights, bias, transposed MLP weights
__global__ void k_prep(const float* __restrict__ w_ih, const float* __restrict__ w_hh,
                       const float* __restrict__ b_ih, const float* __restrict__ b_hh,
                       const float* __restrict__ w1, const float* __restrict__ w2,
                       const float* __restrict__ w3) {
    int i = blockIdx.x * blockDim.x + threadIdx.x;
    const int NW2 = KTOT * 256;                 // 135168
    if (i < NW2) {
        int k = i / 256, c = i - k * 256;
        float v0 = wcomb(w_ih, w_hh, 2*c,     k);
        float v1 = wcomb(w_ih, w_hh, 2*c + 1, k);
        d_W2[i] = __floats2half2_rn(v0, v1);
        return;
    }
    int j = i - NW2;
    if (j < GC) {                                // bias
        float v;
        if (j < 256)      v = b_ih[j] + b_hh[j];
        else if (j < 384) v = b_ih[j];
        else              v = b_hh[j - 128];
        d_biasc[j] = v;
        return;
    }
    j -= GC;
    if (j < 128*128) { int k = j >> 7, o = j & 127; d_w1t[k*128 + o] = w1[o*128 + k]; return; }
    j -= 128*128;
    if (j < 128*128) { int k = j >> 7, o = j & 127; d_w2t[k*128 + o] = w2[o*128 + k]; return; }
    j -= 128*128;
    if (j < 128*NBANDS) { int k = j / NBANDS, o = j - k*NBANDS; d_w3t[k*NBANDS + o] = w3[o*128 + k]; }
}

// ---------------- packed L+iR 1024-pt FFT per (b,t) ----------------
__global__ void k_fft(const float* __restrict__ wavL, const float* __restrict__ wavR,
                      float* __restrict__ outXL, float* __restrict__ outXR,
                      int realmode, long long xl_off, long long xr_off, long long out_elems) {
    __shared__ float2 z[1024];
    int bt = blockIdx.x;
    int b = bt / TT, t = bt - b * TT;
    int tid = threadIdx.x;
    const float* wl = wavL + b * FSAMP + t * WINLEN;
    const float* wr = wavR + b * FSAMP + t * WINLEN;

    for (int j = tid; j < 1024; j += 256) {
        float2 v = make_float2(0.f, 0.f);
        if (j < WINLEN) {
            float w = 0.5f - 0.5f * cosf(6.2831853071795864f * (float)j / (float)WINLEN);
            v.x = wl[j] * w; v.y = wr[j] * w;
        }
        z[__brev((unsigned)j) >> 22] = v;
    }
    __syncthreads();

    for (int len = 2; len <= 1024; len <<= 1) {
        int half = len >> 1;
        for (int i = tid; i < 512; i += 256) {
            int j = i & (half - 1);
            int base = ((i - j) << 1) + j;
            float s, c;
            __sincosf(-6.2831853071795864f * (float)j / (float)len, &s, &c);
            float2 u = z[base], v = z[base + half];
            float tr = v.x * c - v.y * s;
            float ti = v.x * s + v.y * c;
            z[base]        = make_float2(u.x + tr, u.y + ti);
            z[base + half] = make_float2(u.x - tr, u.y - ti);
        }
        __syncthreads();
    }

    for (int k = tid; k < FFb; k += 256) {
        float2 zk = z[k];
        float2 zm = z[(1024 - k) & 1023];
        float lr = 0.5f * (zk.x + zm.x), li = 0.5f * (zk.y - zm.y);
        float rr = 0.5f * (zk.y + zm.y), ri = 0.5f * (zm.x - zk.x);
        long long o = (long long)bt * FFb + k;
        if (realmode) {
            outXL[o] = lr;
            outXR[o] = rr;
        } else {
            long long base2 = o * 2;
            if (xl_off + base2 + 1 < out_elems) {
                outXL[base2] = lr; outXL[base2 + 1] = li;
            }
            if (xr_off + base2 + 1 < out_elems) {
                outXR[base2] = rr; outXR[base2 + 1] = ri;
            }
        }
        d_mag[o] = make_float2(sqrtf(lr * lr + li * li), sqrtf(rr * rr + ri * ri));
    }
}

// ---------------- persistent scan: all 19 steps, 2 batch rows per block ----------------
__global__ void __launch_bounds__(NTHR) k_steps(
        float* __restrict__ outYL, float* __restrict__ outYR, float* __restrict__ outQ,
        const float* __restrict__ b1, const float* __restrict__ g1, const float* __restrict__ be1,
        const float* __restrict__ b2, const float* __restrict__ g2, const float* __restrict__ be2,
        const float* __restrict__ b3) {
    // Dynamic smem: gpart (GEMM phase) aliases magc (filter phase); temporally
    // disjoint within a step (filter reads magc; sync; GEMM writes gpart).
    extern __shared__ __align__(16) float dyn[];
    float* gpart = dyn;                                   // [KSPLIT][RPB*GC]
    float2 (*magc)[FFb] = (float2 (*)[FFb])dyn;           // [RPB][FFb]

    __shared__ __half2 a_h2[KTOT];             // GEMM input, (row0,row1) per k
    __shared__ float hold_s[RPB][128];         // fp32 h state
    __shared__ float hbuf[RPB][128];
    __shared__ float abuf[RPB][128];
    __shared__ float Qs[RPB][NBANDS];
    __shared__ float memLs[RPB][NBANDS], memRs[RPB][NBANDS];
    __shared__ float2 lnp[RPB][4];

    int tid = threadIdx.x, lane = tid & 31, wid = tid >> 5;
    int b0 = blockIdx.x * RPB;
    __half* ah = (__half*)a_h2;

    // state init
    for (int i = tid; i < RPB*NBANDS; i += NTHR) {
        int r = i / NBANDS, n = i - r*NBANDS;
        Qs[r][n] = d_q0[n]; memLs[r][n] = 0.f; memRs[r][n] = 0.f;
    }
    if (tid < KTOT) a_h2[tid] = __floats2half2_rn(0.f, 0.f);
    if (tid < RPB*128) hold_s[tid >> 7][tid & 127] = 0.f;
    __syncthreads();

    for (int t = 0; t < TT; t++) {
        // ---- load magnitude rows ----
        for (int i = tid; i < RPB*FFb; i += NTHR) {
            int r = i / FFb, k = i - r*FFb;
            magc[r][k] = d_mag[(long long)((b0 + r)*TT + t)*FFb + k];
        }
        __syncthreads();

        // ---- gammatone filterbank: warp per (row,band) ----
        for (int task = wid; task < RPB*NBANDS; task += 32) {
            int r = task / NBANDS, n = task - r*NBANDS;
            float Q  = Qs[r][n];
            float fc = d_fc[n];
            float bw = fc / (Q + 1e-8f) + 1e-8f;
            float inv = 1.0f / bw;
            float rad = 5.0f * bw;                       // exp(-12.5) tail
            int kmin = (int)ceilf((fc - rad) * 0.064f);  if (kmin < 0)   kmin = 0;
            int kmax = (int)floorf((fc + rad) * 0.064f); if (kmax > 512) kmax = 512;
            float sw = 0.f, sl = 0.f, sr = 0.f;
            for (int k = kmin + lane; k <= kmax; k += 32) {
                float d = ((float)k * 15.625f - fc) * inv;
                float w = __expf(-0.5f * d * d);
                float2 m = magc[r][k];
                sw += w; sl += w * m.x; sr += w * m.y;
            }
#pragma unroll
            for (int off = 16; off; off >>= 1) {
                sw += __shfl_down_sync(0xffffffffu, sw, off);
                sl += __shfl_down_sync(0xffffffffu, sl, off);
                sr += __shfl_down_sync(0xffffffffu, sr, off);
            }
            if (lane == 0) {
                float den = 1.0f / (sw + 1e-8f);
                float yl = sl * den, yr = sr * den;
                long long oi = ((long long)(b0 + r)*TT + t)*NBANDS + n;
                outYL[oi] = yl; outYR[oi] = yr; outQ[oi] = Q;
                float cL = log1pf(fmaxf(yl, 0.f));
                float cR = log1pf(fmaxf(yr, 0.f));
                float mLo = memLs[r][n], mRo = memRs[r][n];
                ah[(n)*2       + r] = __float2half_rn(cL);
                ah[(100 + n)*2 + r] = __float2half_rn(mLo);
                ah[(200 + n)*2 + r] = __float2half_rn(cR);
                ah[(300 + n)*2 + r] = __float2half_rn(mRo);
                memLs[r][n] = 0.8f * mLo + 0.2f * cL;
                memRs[r][n] = 0.8f * mRo + 0.2f * cR;
            }
        }
        __syncthreads();   // filter done reading magc; gpart may clobber it

        // ---- GRU GEMM: warp = (colgroup, k16th); lane = 8 cols, both rows ----
        {
            int cg = wid >> 4, kq = wid & 15;
            int c0 = cg * 128 + lane * 4;                // half2 index
            __half2 acc0[4], acc1[4];
#pragma unroll
            for (int j = 0; j < 4; j++) {
                acc0[j] = __floats2half2_rn(0.f, 0.f);
                acc1[j] = __floats2half2_rn(0.f, 0.f);
            }
            int k0 = kq * 33;
#pragma unroll 3
            for (int k = k0; k < k0 + 33; k++) {
                __half2 av = a_h2[k];
                __half2 a0 = __low2half2(av);            // (row0,row0)
                __half2 a1 = __high2half2(av);           // (row1,row1)
                uint4 w4 = *(const uint4*)&d_W2[k*256 + c0];
                __half2 w0 = *(__half2*)&w4.x, w1 = *(__half2*)&w4.y;
                __half2 w2 = *(__half2*)&w4.z, w3 = *(__half2*)&w4.w;
                acc0[0] = __hfma2(w0, a0, acc0[0]); acc1[0] = __hfma2(w0, a1, acc1[0]);
                acc0[1] = __hfma2(w1, a0, acc0[1]); acc1[1] = __hfma2(w1, a1, acc1[1]);
                acc0[2] = __hfma2(w2, a0, acc0[2]); acc1[2] = __hfma2(w2, a1, acc1[2]);
                acc0[3] = __hfma2(w3, a0, acc0[3]); acc1[3] = __hfma2(w3, a1, acc1[3]);
            }
            float* gp0 = gpart + kq*(RPB*GC) + cg*256 + lane*8;      // row0
            float* gp1 = gp0 + GC;                                    // row1
            float2 f0 = __half22float2(acc0[0]), f1 = __half22float2(acc0[1]);
            float2 f2 = __half22float2(acc0[2]), f3 = __half22float2(acc0[3]);
            *(float4*)gp0       = make_float4(f0.x, f0.y, f1.x, f1.y);
            *(float4*)(gp0 + 4) = make_float4(f2.x, f2.y, f3.x, f3.y);
            f0 = __half22float2(acc1[0]); f1 = __half22float2(acc1[1]);
            f2 = __half22float2(acc1[2]); f3 = __half22float2(acc1[3]);
            *(float4*)gp1       = make_float4(f0.x, f0.y, f1.x, f1.y);
            *(float4*)(gp1 + 4) = make_float4(f2.x, f2.y, f3.x, f3.y);
        }
        __syncthreads();

        // ---- fused split-K reduce + GRU gating ----
        if (tid < RPB*128) {
            int row = tid >> 7, d = tid & 127;
            float gr = d_biasc[d], gz = d_biasc[128 + d];
            float gin = d_biasc[256 + d], ghn = d_biasc[384 + d];
#pragma unroll
            for (int q = 0; q < KSPLIT; q++) {
                const float* base = gpart + q*(RPB*GC) + row*GC;
                gr  += base[d];       gz  += base[128 + d];
                gin += base[256 + d]; ghn += base[384 + d];
            }
            float rg = 1.f / (1.f + __expf(-gr));
            float zg = 1.f / (1.f + __expf(-gz));
            float ng = tanhf(gin + rg * ghn);
            float hn = (1.f - zg) * ng + zg * hold_s[row][d];
            hold_s[row][d] = hn;
            hbuf[row][d] = hn;
            ah[(400 + d)*2 + row] = __float2half_rn(hn);
        }
        __syncthreads();

        // ---- MLP layer 1 (Linear + LN + SiLU) ----
        float v1 = 0.f;
        if (tid < RPB*128) {
            int row = tid >> 7, o = tid & 127;
            float a0 = 0.f, a1 = 0.f, a2 = 0.f, a3 = 0.f;
#pragma unroll 8
            for (int k = 0; k < 128; k += 4) {
                a0 += hbuf[row][k]   * d_w1t[k*128 + o];
                a1 += hbuf[row][k+1] * d_w1t[(k+1)*128 + o];
                a2 += hbuf[row][k+2] * d_w1t[(k+2)*128 + o];
                a3 += hbuf[row][k+3] * d_w1t[(k+3)*128 + o];
            }
            v1 = b1[o] + (a0 + a1) + (a2 + a3);
            float s1 = v1, s2 = v1 * v1;
#pragma unroll
            for (int off = 16; off; off >>= 1) {
                s1 += __shfl_down_sync(0xffffffffu, s1, off);
                s2 += __shfl_down_sync(0xffffffffu, s2, off);
            }
            if (lane == 0) lnp[row][wid & 3] = make_float2(s1, s2);
        }
        __syncthreads();
        if (tid < RPB*128) {
            int row = tid >> 7, o = tid & 127;
            float S1 = 0.f, S2 = 0.f;
#pragma unroll
            for (int j = 0; j < 4; j++) { S1 += lnp[row][j].x; S2 += lnp[row][j].y; }
            float mean = S1 * (1.f/128.f);
            float var  = S2 * (1.f/128.f) - mean * mean;
            float isd  = rsqrtf(var + 1e-5f);
            float x = (v1 - mean) * isd * g1[o] + be1[o];
            abuf[row][o] = x / (1.f + __expf(-x));
        }
        __syncthreads();

        // ---- MLP layer 2 ----
        float v2 = 0.f;
        if (tid < RPB*128) {
            int row = tid >> 7, o = tid & 127;
            float a0 = 0.f, a1 = 0.f, a2 = 0.f, a3 = 0.f;
#pragma unroll 8
            for (int k = 0; k < 128; k += 4) {
                a0 += abuf[row][k]   * d_w2t[k*128 + o];
                a1 += abuf[row][k+1] * d_w2t[(k+1)*128 + o];
                a2 += abuf[row][k+2] * d_w2t[(k+2)*128 + o];
                a3 += abuf[row][k+3] * d_w2t[(k+3)*128 + o];
            }
            v2 = b2[o] + (a0 + a1) + (a2 + a3);
            float s1 = v2, s2 = v2 * v2;
#pragma unroll
            for (int off = 16; off; off >>= 1) {
                s1 += __shfl_down_sync(0xffffffffu, s1, off);
                s2 += __shfl_down_sync(0xffffffffu, s2, off);
            }
            if (lane == 0) lnp[row][wid & 3] = make_float2(s1, s2);
        }
        __syncthreads();
        if (tid < RPB*128) {
            int row = tid >> 7, o = tid & 127;
            float S1 = 0.f, S2 = 0.f;
#pragma unroll
            for (int j = 0; j < 4; j++) { S1 += lnp[row][j].x; S2 += lnp[row][j].y; }
            float mean = S1 * (1.f/128.f);
            float var  = S2 * (1.f/128.f) - mean * mean;
            float isd  = rsqrtf(var + 1e-5f);
            float x = (v2 - mean) * isd * g2[o] + be2[o];
            hbuf[row][o] = x / (1.f + __expf(-x));
        }
        __syncthreads();

        // ---- head + Q update ----
        if (tid < RPB*NBANDS) {
            int row = tid / NBANDS, o = tid - row*NBANDS;
            float a0 = 0.f, a1 = 0.f, a2 = 0.f, a3 = 0.f;
#pragma unroll 8
            for (int k = 0; k < 128; k += 4) {
                a0 += hbuf[row][k]   * d_w3t[k*NBANDS + o];
                a1 += hbuf[row][k+1] * d_w3t[(k+1)*NBANDS + o];
                a2 += hbuf[row][k+2] * d_w3t[(k+2)*NBANDS + o];
                a3 += hbuf[row][k+3] * d_w3t[(k+3)*NBANDS + o];
            }
            float delta = tanhf(b3[o] + (a0 + a1) + (a2 + a3));
            float qt = d_q0[o] + delta * d_dq[o];
            float qn = 0.8f * Qs[row][o] + 0.2f * qt;
            Qs[row][o] = fminf(fmaxf(qn, 0.05f), 30.f);
        }
        __syncthreads();
    }
}

// ---------------- launch ----------------
extern "C" void kernel_launch(void* const* d_in, const int* in_sizes, int n_in,
                              void* d_out, int out_size) {
    const float* wavL = (const float*)d_in[0];
    const float* wavR = (const float*)d_in[1];
    const float* w_ih = (const float*)d_in[2];
    const float* w_hh = (const float*)d_in[3];
    const float* b_ih = (const float*)d_in[4];
    const float* b_hh = (const float*)d_in[5];
    const float* w1  = (const float*)d_in[6];
    const float* b1  = (const float*)d_in[7];
    const float* g1  = (const float*)d_in[8];
    const float* be1 = (const float*)d_in[9];
    const float* w2  = (const float*)d_in[10];
    const float* b2  = (const float*)d_in[11];
    const float* g2  = (const float*)d_in[12];
    const float* be2 = (const float*)d_in[13];
    const float* w3  = (const float*)d_in[14];
    const float* b3  = (const float*)d_in[15];

    long long out_elems = (long long)out_size;
    const long long NYQ = 3LL * BB * TT * NBANDS;       // 1,459,200
    const long long XSZ = (long long)BB * TT * FFb;     // 2,495,232 per X (real plane)
    int realmode = (out_elems < NYQ + 3 * XSZ) ? 1 : 0;

    float* out = (float*)d_out;
    float* outYL = out;
    float* outYR = outYL + (long long)BB * TT * NBANDS;
    float* outQ  = outYR + (long long)BB * TT * NBANDS;
    long long xl_off = NYQ;
    long long xr_off = realmode ? (NYQ + XSZ) : (NYQ + 2 * XSZ);
    float* outXL = out + xl_off;
    float* outXR = out + xr_off;

    cudaFuncSetAttribute(k_steps, cudaFuncAttributeMaxDynamicSharedMemorySize, DYN_SMEM);

    const int PREP_N = KTOT*256 + GC + 128*128 + 128*128 + 128*NBANDS;
    k_consts<<<1, 128>>>();
    k_prep<<<(PREP_N + 255) / 256, 256>>>(w_ih, w_hh, b_ih, b_hh, w1, w2, w3);
    k_fft<<<BB * TT, 256>>>(wavL, wavR, outXL, outXR, realmode, xl_off, xr_off, out_elems);
    k_steps<<<NBLK, NTHR, DYN_SMEM>>>(outYL, outYR, outQ, b1, g1, be1, b2, g2, be2, b3);
}

// round 9
// speedup vs baseline: 4.9875x; 1.1086x over previous
#include <cuda_runtime.h>
#include <cuda_fp16.h>

#define NBANDS 100
#define TT 19
#define FFb 513
#define BB 256
#define KTOT 528          // 400 feat + 128 h
#define GC 512            // combined gate columns: rz(256) | i_n(128) | h_n(128)
#define WINLEN 842
#define FSAMP 16000
#define RPB 2             // batch rows per block
#define NBLK (BB/RPB)     // 128 blocks
#define NTHR 1024
#define KSPLIT 16         // split-K ways (33 k each)
#define DYN_SMEM (KSPLIT*RPB*GC*4)   // 64 KB fp32 partials (aliases mag cache)

// ---------------- device state / scratch ----------------
__device__ float d_fc[NBANDS], d_q0[NBANDS], d_dq[NBANDS];
__device__ __align__(16) __half2 d_W2[KTOT*256];   // [k][colpair], cols (2c,2c+1)
__device__ float d_biasc[GC];
__device__ __align__(16) float2 d_mag[BB*TT*FFb];  // (|L|,|R|)

// ---------------- constants (ERB scale) ----------------
__global__ void k_consts() {
    int n = threadIdx.x;
    if (n < NBANDS) {
        double E0 = 21.4 * log10(4.37 * 50.0   / 1000.0 + 1.0);
        double E1 = 21.4 * log10(4.37 * 7200.0 / 1000.0 + 1.0);
        double E  = E0 + (E1 - E0) * ((double)n / 99.0);
        double fc = (pow(10.0, E / 21.4) - 1.0) * 1000.0 / 4.37;
        double erb = 24.7 * (4.37 * fc / 1000.0 + 1.0);
        double q0 = fc / (1.019 * erb);
        double En = (E - E0) / (E1 - E0 + 1e-12);
        double dq = 2.0 * (0.5 + 0.5 * En);
        if (dq < 0.001) dq = 0.001;
        d_fc[n] = (float)fc; d_q0[n] = (float)q0; d_dq[n] = (float)dq;
    }
}

__device__ __forceinline__ float wcomb(const float* w_ih, const float* w_hh, int col, int k) {
    if (col < 256) return (k < 400) ? w_ih[col*400 + k] : w_hh[col*128 + (k-400)];
    if (col < 384) return (k < 400) ? w_ih[col*400 + k] : 0.f;
    return (k < 400) ? 0.f : w_hh[(col-128)*128 + (k-400)];
}

// Build fp16 combined GRU weights + bias
__global__ void k_prep(const float* __restrict__ w_ih, const float* __restrict__ w_hh,
                       const float* __restrict__ b_ih, const float* __restrict__ b_hh) {
    int i = blockIdx.x * blockDim.x + threadIdx.x;
    const int NW2 = KTOT * 256;                 // 135168
    if (i < NW2) {
        int k = i / 256, c = i - k * 256;
        float v0 = wcomb(w_ih, w_hh, 2*c,     k);
        float v1 = wcomb(w_ih, w_hh, 2*c + 1, k);
        d_W2[i] = __floats2half2_rn(v0, v1);
        return;
    }
    int j = i - NW2;
    if (j < GC) {
        float v;
        if (j < 256)      v = b_ih[j] + b_hh[j];
        else if (j < 384) v = b_ih[j];
        else              v = b_hh[j - 128];
        d_biasc[j] = v;
    }
}

// ---------------- packed L+iR 1024-pt FFT per (b,t), smem twiddles ----------------
__global__ void k_fft(const float* __restrict__ wavL, const float* __restrict__ wavR,
                      float* __restrict__ outXL, float* __restrict__ outXR,
                      int realmode, long long xl_off, long long xr_off, long long out_elems) {
    __shared__ float2 z[1024];
    __shared__ float2 twt[1023];               // stage-contiguous: base = half-1
    int bt = blockIdx.x;
    int b = bt / TT, t = bt - b * TT;
    int tid = threadIdx.x;
    const float* wl = wavL + b * FSAMP + t * WINLEN;
    const float* wr = wavR + b * FSAMP + t * WINLEN;

    for (int g = tid; g < 1023; g += 256) {
        int hb = 31 - __clz(g + 1);
        int half = 1 << hb;
        int j = g + 1 - half;
        float s, c;
        __sincosf(-3.14159265358979f * (float)j / (float)half, &s, &c);
        twt[g] = make_float2(c, s);
    }
    for (int j = tid; j < 1024; j += 256) {
        float2 v = make_float2(0.f, 0.f);
        if (j < WINLEN) {
            float w = 0.5f - 0.5f * cosf(6.2831853071795864f * (float)j / (float)WINLEN);
            v.x = wl[j] * w; v.y = wr[j] * w;
        }
        z[__brev((unsigned)j) >> 22] = v;
    }
    __syncthreads();

    for (int len = 2; len <= 1024; len <<= 1) {
        int half = len >> 1;
        for (int i = tid; i < 512; i += 256) {
            int j = i & (half - 1);
            int base = ((i - j) << 1) + j;
            float2 w2 = twt[half - 1 + j];
            float c = w2.x, s = w2.y;
            float2 u = z[base], v = z[base + half];
            float tr = v.x * c - v.y * s;
            float ti = v.x * s + v.y * c;
            z[base]        = make_float2(u.x + tr, u.y + ti);
            z[base + half] = make_float2(u.x - tr, u.y - ti);
        }
        __syncthreads();
    }

    for (int k = tid; k < FFb; k += 256) {
        float2 zk = z[k];
        float2 zm = z[(1024 - k) & 1023];
        float lr = 0.5f * (zk.x + zm.x), li = 0.5f * (zk.y - zm.y);
        float rr = 0.5f * (zk.y + zm.y), ri = 0.5f * (zm.x - zk.x);
        long long o = (long long)bt * FFb + k;
        if (realmode) {
            outXL[o] = lr;
            outXR[o] = rr;
        } else {
            long long base2 = o * 2;
            if (xl_off + base2 + 1 < out_elems) {
                outXL[base2] = lr; outXL[base2 + 1] = li;
            }
            if (xr_off + base2 + 1 < out_elems) {
                outXR[base2] = rr; outXR[base2 + 1] = ri;
            }
        }
        d_mag[o] = make_float2(sqrtf(lr * lr + li * li), sqrtf(rr * rr + ri * ri));
    }
}

// ---------------- persistent scan: all 19 steps, 2 batch rows per block ----------------
__global__ void __launch_bounds__(NTHR) k_steps(
        float* __restrict__ outYL, float* __restrict__ outYR, float* __restrict__ outQ,
        const float* __restrict__ w1, const float* __restrict__ b1,
        const float* __restrict__ g1, const float* __restrict__ be1,
        const float* __restrict__ w2, const float* __restrict__ b2,
        const float* __restrict__ g2, const float* __restrict__ be2,
        const float* __restrict__ w3, const float* __restrict__ b3) {
    extern __shared__ __align__(16) float dyn[];
    float* gpart = dyn;                                   // [KSPLIT][RPB*GC] (swizzled cols)
    float2 (*magc)[FFb] = (float2 (*)[FFb])dyn;           // [RPB][FFb] (aliased)

    __shared__ __half2 a_h2[KTOT];             // GEMM input, (row0,row1) per k
    __shared__ float hold_s[RPB][128];         // fp32 h state
    __shared__ __align__(16) float hbuf[RPB][128];
    __shared__ __align__(16) float abuf[RPB][128];
    __shared__ float Qs[RPB][NBANDS];
    __shared__ float memLs[RPB][NBANDS], memRs[RPB][NBANDS];
    __shared__ float2 lnp[RPB][16];

    int tid = threadIdx.x, lane = tid & 31, wid = tid >> 5;
    int b0 = blockIdx.x * RPB;
    __half* ah = (__half*)a_h2;

    // thread mapping for 4-way split-K phases
    int mrow = tid >> 9;                // 0..1
    int mo   = (tid >> 2) & 127;        // output index
    int mks  = tid & 3;                 // k-split lane

    // state init
    for (int i = tid; i < RPB*NBANDS; i += NTHR) {
        int r = i / NBANDS, n = i - r*NBANDS;
        Qs[r][n] = d_q0[n]; memLs[r][n] = 0.f; memRs[r][n] = 0.f;
    }
    if (tid < KTOT) a_h2[tid] = __floats2half2_rn(0.f, 0.f);
    if (tid < RPB*128) hold_s[tid >> 7][tid & 127] = 0.f;
    __syncthreads();

    for (int t = 0; t < TT; t++) {
        // ---- load magnitude rows ----
        for (int i = tid; i < RPB*FFb; i += NTHR) {
            int r = i / FFb, k = i - r*FFb;
            magc[r][k] = d_mag[(long long)((b0 + r)*TT + t)*FFb + k];
        }
        __syncthreads();

        // ---- gammatone filterbank: warp per (row,band), Gaussian recurrence ----
        for (int task = wid; task < RPB*NBANDS; task += 32) {
            int r = task / NBANDS, n = task - r*NBANDS;
            float Q  = Qs[r][n];
            float fc = d_fc[n];
            float bw = fc / (Q + 1e-8f) + 1e-8f;
            float inv = 1.0f / bw;
            float rad = 5.0f * bw;
            int kmin = (int)ceilf((fc - rad) * 0.064f);  if (kmin < 0)   kmin = 0;
            int kmax = (int)floorf((fc + rad) * 0.064f); if (kmax > 512) kmax = 512;
            float Dlt = 500.f * inv;                 // 32 bins * 15.625 Hz, in sigma units
            float c1 = __expf(-0.5f * Dlt * Dlt);
            float c2 = c1 * c1;
            int k = kmin + lane;
            float d0 = ((float)k * 15.625f - fc) * inv;
            float w  = __expf(-0.5f * d0 * d0);
            float u  = __expf(-d0 * Dlt);
            float sw = 0.f, sl = 0.f, sr = 0.f;
            for (; k <= kmax; k += 32) {
                float2 m = magc[r][k];
                sw += w; sl = fmaf(w, m.x, sl); sr = fmaf(w, m.y, sr);
                w = (w * c1) * u;                    // w_{i+1} = w_i exp(-d\Delta - \Delta^2/2)
                u *= c2;                             // u_{i+1} = u_i exp(-\Delta^2)
            }
#pragma unroll
            for (int off = 16; off; off >>= 1) {
                sw += __shfl_down_sync(0xffffffffu, sw, off);
                sl += __shfl_down_sync(0xffffffffu, sl, off);
                sr += __shfl_down_sync(0xffffffffu, sr, off);
            }
            if (lane == 0) {
                float den = 1.0f / (sw + 1e-8f);
                float yl = sl * den, yr = sr * den;
                long long oi = ((long long)(b0 + r)*TT + t)*NBANDS + n;
                outYL[oi] = yl; outYR[oi] = yr; outQ[oi] = Q;
                float cL = log1pf(fmaxf(yl, 0.f));
                float cR = log1pf(fmaxf(yr, 0.f));
                float mLo = memLs[r][n], mRo = memRs[r][n];
                ah[(n)*2       + r] = __float2half_rn(cL);
                ah[(100 + n)*2 + r] = __float2half_rn(mLo);
                ah[(200 + n)*2 + r] = __float2half_rn(cR);
                ah[(300 + n)*2 + r] = __float2half_rn(mRo);
                memLs[r][n] = 0.8f * mLo + 0.2f * cL;
                memRs[r][n] = 0.8f * mRo + 0.2f * cR;
            }
        }
        __syncthreads();   // filter done reading magc; gpart may clobber it

        // ---- GRU GEMM: warp = (colgroup, k16th); lane = 8 cols, both rows ----
        {
            int cg = wid >> 4, kq = wid & 15;
            int c0 = cg * 128 + lane * 4;                // half2 index
            __half2 acc0[4], acc1[4];
#pragma unroll
            for (int j = 0; j < 4; j++) {
                acc0[j] = __floats2half2_rn(0.f, 0.f);
                acc1[j] = __floats2half2_rn(0.f, 0.f);
            }
            int k0 = kq * 33;
#pragma unroll 3
            for (int k = k0; k < k0 + 33; k++) {
                __half2 av = a_h2[k];
                __half2 a0 = __low2half2(av);
                __half2 a1 = __high2half2(av);
                uint4 w4 = *(const uint4*)&d_W2[k*256 + c0];
                __half2 w0 = *(__half2*)&w4.x, w1h = *(__half2*)&w4.y;
                __half2 w2h = *(__half2*)&w4.z, w3h = *(__half2*)&w4.w;
                acc0[0] = __hfma2(w0, a0, acc0[0]);  acc1[0] = __hfma2(w0, a1, acc1[0]);
                acc0[1] = __hfma2(w1h, a0, acc0[1]); acc1[1] = __hfma2(w1h, a1, acc1[1]);
                acc0[2] = __hfma2(w2h, a0, acc0[2]); acc1[2] = __hfma2(w2h, a1, acc1[2]);
                acc0[3] = __hfma2(w3h, a0, acc0[3]); acc1[3] = __hfma2(w3h, a1, acc1[3]);
            }
            int cb = cg * 256 + lane * 8;
            int cw = (cb + kq * 8) & (GC - 1);           // swizzle (8-aligned, no wrap mid-span)
            float* gp0 = gpart + kq*(RPB*GC) + cw;       // row0
            float* gp1 = gp0 + GC;                       // row1
            float2 f0 = __half22float2(acc0[0]), f1 = __half22float2(acc0[1]);
            float2 f2 = __half22float2(acc0[2]), f3 = __half22float2(acc0[3]);
            *(float4*)gp0       = make_float4(f0.x, f0.y, f1.x, f1.y);
            *(float4*)(gp0 + 4) = make_float4(f2.x, f2.y, f3.x, f3.y);
            f0 = __half22float2(acc1[0]); f1 = __half22float2(acc1[1]);
            f2 = __half22float2(acc1[2]); f3 = __half22float2(acc1[3]);
            *(float4*)gp1       = make_float4(f0.x, f0.y, f1.x, f1.y);
            *(float4*)(gp1 + 4) = make_float4(f2.x, f2.y, f3.x, f3.y);
        }
        __syncthreads();

        // ---- fused split-K reduce + GRU gating (all 1024 threads, 4-way) ----
        {
            int d = mo;                                  // 0..127
            float gr = 0.f, gz = 0.f, gin = 0.f, ghn = 0.f;
#pragma unroll
            for (int i = 0; i < 4; i++) {
                int q = mks + i * 4;
                const float* base = gpart + q*(RPB*GC) + mrow*GC;
                int sw8 = q * 8;
                gr  += base[(d       + sw8) & (GC-1)];
                gz  += base[(128 + d + sw8) & (GC-1)];
                gin += base[(256 + d + sw8) & (GC-1)];
                ghn += base[(384 + d + sw8) & (GC-1)];
            }
            gr  += __shfl_xor_sync(0xffffffffu, gr, 1);  gr  += __shfl_xor_sync(0xffffffffu, gr, 2);
            gz  += __shfl_xor_sync(0xffffffffu, gz, 1);  gz  += __shfl_xor_sync(0xffffffffu, gz, 2);
            gin += __shfl_xor_sync(0xffffffffu, gin, 1); gin += __shfl_xor_sync(0xffffffffu, gin, 2);
            ghn += __shfl_xor_sync(0xffffffffu, ghn, 1); ghn += __shfl_xor_sync(0xffffffffu, ghn, 2);
            if (mks == 0) {
                gr += d_biasc[d]; gz += d_biasc[128 + d];
                gin += d_biasc[256 + d]; ghn += d_biasc[384 + d];
                float rg = 1.f / (1.f + __expf(-gr));
                float zg = 1.f / (1.f + __expf(-gz));
                float ng = tanhf(gin + rg * ghn);
                float hn = (1.f - zg) * ng + zg * hold_s[mrow][d];
                hold_s[mrow][d] = hn;
                hbuf[mrow][d] = hn;
                ah[(400 + d)*2 + mrow] = __float2half_rn(hn);
            }
        }
        __syncthreads();

        // ---- MLP layer 1: v = hbuf @ w1^T (4-way split-K, all threads) ----
        float v1;
        {
            float acc = 0.f;
            const float* wr_ = w1 + mo*128 + mks*4;
#pragma unroll
            for (int j = 0; j < 8; j++) {
                float4 wv = *(const float4*)(wr_ + j*16);
                float4 hv = *(const float4*)&hbuf[mrow][j*16 + mks*4];
                acc += wv.x*hv.x + wv.y*hv.y + wv.z*hv.z + wv.w*hv.w;
            }
            acc += __shfl_xor_sync(0xffffffffu, acc, 1);
            acc += __shfl_xor_sync(0xffffffffu, acc, 2);
            v1 = acc + b1[mo];
            float s1 = v1, s2 = v1 * v1;
#pragma unroll
            for (int off = 16; off; off >>= 1) {
                s1 += __shfl_down_sync(0xffffffffu, s1, off);
                s2 += __shfl_down_sync(0xffffffffu, s2, off);
            }
            if (lane == 0) lnp[mrow][wid & 15] = make_float2(s1, s2);
        }
        __syncthreads();
        {
            float S1 = 0.f, S2 = 0.f;
#pragma unroll
            for (int j = 0; j < 16; j++) { float2 p = lnp[mrow][j]; S1 += p.x; S2 += p.y; }
            float mean = S1 * (1.f/512.f);               // 128 outputs x4 redundancy
            float var  = S2 * (1.f/512.f) - mean * mean;
            float isd  = rsqrtf(var + 1e-5f);
            float x = (v1 - mean) * isd * g1[mo] + be1[mo];
            if (mks == 0) abuf[mrow][mo] = x / (1.f + __expf(-x));
        }
        __syncthreads();

        // ---- MLP layer 2 ----
        float v2;
        {
            float acc = 0.f;
            const float* wr_ = w2 + mo*128 + mks*4;
#pragma unroll
            for (int j = 0; j < 8; j++) {
                float4 wv = *(const float4*)(wr_ + j*16);
                float4 hv = *(const float4*)&abuf[mrow][j*16 + mks*4];
                acc += wv.x*hv.x + wv.y*hv.y + wv.z*hv.z + wv.w*hv.w;
            }
            acc += __shfl_xor_sync(0xffffffffu, acc, 1);
            acc += __shfl_xor_sync(0xffffffffu, acc, 2);
            v2 = acc + b2[mo];
            float s1 = v2, s2 = v2 * v2;
#pragma unroll
            for (int off = 16; off; off >>= 1) {
                s1 += __shfl_down_sync(0xffffffffu, s1, off);
                s2 += __shfl_down_sync(0xffffffffu, s2, off);
            }
            if (lane == 0) lnp[mrow][wid & 15] = make_float2(s1, s2);
        }
        __syncthreads();
        {
            float S1 = 0.f, S2 = 0.f;
#pragma unroll
            for (int j = 0; j < 16; j++) { float2 p = lnp[mrow][j]; S1 += p.x; S2 += p.y; }
            float mean = S1 * (1.f/512.f);
            float var  = S2 * (1.f/512.f) - mean * mean;
            float isd  = rsqrtf(var + 1e-5f);
            float x = (v2 - mean) * isd * g2[mo] + be2[mo];
            if (mks == 0) hbuf[mrow][mo] = x / (1.f + __expf(-x));
        }
        __syncthreads();

        // ---- head + Q update: 800 threads, 4-way split-K ----
        if (tid < 800) {
            int row = tid / 400;
            int rem = tid - row * 400;
            int o = rem >> 2, ks = rem & 3;
            float acc = 0.f;
            const float* wr_ = w3 + o*128 + ks*4;
#pragma unroll
            for (int j = 0; j < 8; j++) {
                float4 wv = *(const float4*)(wr_ + j*16);
                float4 hv = *(const float4*)&hbuf[row][j*16 + ks*4];
                acc += wv.x*hv.x + wv.y*hv.y + wv.z*hv.z + wv.w*hv.w;
            }
            acc += __shfl_xor_sync(0xffffffffu, acc, 1);
            acc += __shfl_xor_sync(0xffffffffu, acc, 2);
            if (ks == 0) {
                float delta = tanhf(acc + b3[o]);
                float qt = d_q0[o] + delta * d_dq[o];
                float qn = 0.8f * Qs[row][o] + 0.2f * qt;
                Qs[row][o] = fminf(fmaxf(qn, 0.05f), 30.f);
            }
        }
        __syncthreads();
    }
}

// ---------------- launch ----------------
extern "C" void kernel_launch(void* const* d_in, const int* in_sizes, int n_in,
                              void* d_out, int out_size) {
    const float* wavL = (const float*)d_in[0];
    const float* wavR = (const float*)d_in[1];
    const float* w_ih = (const float*)d_in[2];
    const float* w_hh = (const float*)d_in[3];
    const float* b_ih = (const float*)d_in[4];
    const float* b_hh = (const float*)d_in[5];
    const float* w1  = (const float*)d_in[6];
    const float* b1  = (const float*)d_in[7];
    const float* g1  = (const float*)d_in[8];
    const float* be1 = (const float*)d_in[9];
    const float* w2  = (const float*)d_in[10];
    const float* b2  = (const float*)d_in[11];
    const float* g2  = (const float*)d_in[12];
    const float* be2 = (const float*)d_in[13];
    const float* w3  = (const float*)d_in[14];
    const float* b3  = (const float*)d_in[15];

    long long out_elems = (long long)out_size;
    const long long NYQ = 3LL * BB * TT * NBANDS;       // 1,459,200
    const long long XSZ = (long long)BB * TT * FFb;     // 2,495,232 per X (real plane)
    int realmode = (out_elems < NYQ + 3 * XSZ) ? 1 : 0;

    float* out = (float*)d_out;
    float* outYL = out;
    float* outYR = outYL + (long long)BB * TT * NBANDS;
    float* outQ  = outYR + (long long)BB * TT * NBANDS;
    long long xl_off = NYQ;
    long long xr_off = realmode ? (NYQ + XSZ) : (NYQ + 2 * XSZ);
    float* outXL = out + xl_off;
    float* outXR = out + xr_off;

    cudaFuncSetAttribute(k_steps, cudaFuncAttributeMaxDynamicSharedMemorySize, DYN_SMEM);

    const int PREP_N = KTOT*256 + GC;
    k_consts<<<1, 128>>>();
    k_prep<<<(PREP_N + 255) / 256, 256>>>(w_ih, w_hh, b_ih, b_hh);
    k_fft<<<BB * TT, 256>>>(wavL, wavR, outXL, outXR, realmode, xl_off, xr_off, out_elems);
    k_steps<<<NBLK, NTHR, DYN_SMEM>>>(outYL, outYR, outQ,
                                      w1, b1, g1, be1, w2, b2, g2, be2, w3, b3);
}

// round 11
// speedup vs baseline: 5.0079x; 1.0041x over previous
#include <cuda_runtime.h>
#include <cuda_fp16.h>

#define NBANDS 100
#define TT 19
#define FFb 513
#define BB 256
#define KTOT 528          // 400 feat + 128 h
#define GC 512            // combined gate columns: rz(256) | i_n(128) | h_n(128)
#define WINLEN 842
#define FSAMP 16000
#define RPB 2             // batch rows per block
#define NBLK (BB/RPB)     // 128 blocks
#define NTHR 1024
#define KSPLIT 16         // split-K ways (33 k each)
#define DYN_SMEM (KSPLIT*RPB*GC*4)   // 64 KB fp32 partials (aliases mag cache)

// ---------------- device state / scratch ----------------
__device__ float d_fc[NBANDS], d_q0[NBANDS], d_dq[NBANDS];
__device__ __align__(16) __half2 d_W2[KTOT*256];   // [k][colpair], cols (2c,2c+1)
__device__ float d_biasc[GC];
__device__ __align__(16) float2 d_mag[BB*TT*FFb];  // (|L|,|R|)

// ---------------- constants (ERB scale) ----------------
__global__ void k_consts() {
    int n = threadIdx.x;
    if (n < NBANDS) {
        double E0 = 21.4 * log10(4.37 * 50.0   / 1000.0 + 1.0);
        double E1 = 21.4 * log10(4.37 * 7200.0 / 1000.0 + 1.0);
        double E  = E0 + (E1 - E0) * ((double)n / 99.0);
        double fc = (pow(10.0, E / 21.4) - 1.0) * 1000.0 / 4.37;
        double erb = 24.7 * (4.37 * fc / 1000.0 + 1.0);
        double q0 = fc / (1.019 * erb);
        double En = (E - E0) / (E1 - E0 + 1e-12);
        double dq = 2.0 * (0.5 + 0.5 * En);
        if (dq < 0.001) dq = 0.001;
        d_fc[n] = (float)fc; d_q0[n] = (float)q0; d_dq[n] = (float)dq;
    }
}

__device__ __forceinline__ float wcomb(const float* w_ih, const float* w_hh, int col, int k) {
    if (col < 256) return (k < 400) ? w_ih[col*400 + k] : w_hh[col*128 + (k-400)];
    if (col < 384) return (k < 400) ? w_ih[col*400 + k] : 0.f;
    return (k < 400) ? 0.f : w_hh[(col-128)*128 + (k-400)];
}

// Build fp16 combined GRU weights + bias
__global__ void k_prep(const float* __restrict__ w_ih, const float* __restrict__ w_hh,
                       const float* __restrict__ b_ih, const float* __restrict__ b_hh) {
    int i = blockIdx.x * blockDim.x + threadIdx.x;
    const int NW2 = KTOT * 256;                 // 135168
    if (i < NW2) {
        int k = i / 256, c = i - k * 256;
        float v0 = wcomb(w_ih, w_hh, 2*c,     k);
        float v1 = wcomb(w_ih, w_hh, 2*c + 1, k);
        d_W2[i] = __floats2half2_rn(v0, v1);
        return;
    }
    int j = i - NW2;
    if (j < GC) {
        float v;
        if (j < 256)      v = b_ih[j] + b_hh[j];
        else if (j < 384) v = b_ih[j];
        else              v = b_hh[j - 128];
        d_biasc[j] = v;
    }
}

// ---------------- packed L+iR 1024-pt FFT per (b,t), smem twiddles ----------------
__global__ void k_fft(const float* __restrict__ wavL, const float* __restrict__ wavR,
                      float* __restrict__ outXL, float* __restrict__ outXR,
                      int realmode, long long xl_off, long long xr_off, long long out_elems) {
    __shared__ float2 z[1024];
    __shared__ float2 twt[1023];               // stage-contiguous: base = half-1
    int bt = blockIdx.x;
    int b = bt / TT, t = bt - b * TT;
    int tid = threadIdx.x;
    const float* wl = wavL + b * FSAMP + t * WINLEN;
    const float* wr = wavR + b * FSAMP + t * WINLEN;

    for (int g = tid; g < 1023; g += 256) {
        int hb = 31 - __clz(g + 1);
        int half = 1 << hb;
        int j = g + 1 - half;
        float s, c;
        __sincosf(-3.14159265358979f * (float)j / (float)half, &s, &c);
        twt[g] = make_float2(c, s);
    }
    for (int j = tid; j < 1024; j += 256) {
        float2 v = make_float2(0.f, 0.f);
        if (j < WINLEN) {
            float w = 0.5f - 0.5f * cosf(6.2831853071795864f * (float)j / (float)WINLEN);
            v.x = wl[j] * w; v.y = wr[j] * w;
        }
        z[__brev((unsigned)j) >> 22] = v;
    }
    __syncthreads();

    for (int len = 2; len <= 1024; len <<= 1) {
        int half = len >> 1;
        for (int i = tid; i < 512; i += 256) {
            int j = i & (half - 1);
            int base = ((i - j) << 1) + j;
            float2 w2 = twt[half - 1 + j];
            float c = w2.x, s = w2.y;
            float2 u = z[base], v = z[base + half];
            float tr = v.x * c - v.y * s;
            float ti = v.x * s + v.y * c;
            z[base]        = make_float2(u.x + tr, u.y + ti);
            z[base + half] = make_float2(u.x - tr, u.y - ti);
        }
        __syncthreads();
    }

    for (int k = tid; k < FFb; k += 256) {
        float2 zk = z[k];
        float2 zm = z[(1024 - k) & 1023];
        float lr = 0.5f * (zk.x + zm.x), li = 0.5f * (zk.y - zm.y);
        float rr = 0.5f * (zk.y + zm.y), ri = 0.5f * (zm.x - zk.x);
        long long o = (long long)bt * FFb + k;
        if (realmode) {
            outXL[o] = lr;
            outXR[o] = rr;
        } else {
            long long base2 = o * 2;
            if (xl_off + base2 + 1 < out_elems) {
                outXL[base2] = lr; outXL[base2 + 1] = li;
            }
            if (xr_off + base2 + 1 < out_elems) {
                outXR[base2] = rr; outXR[base2 + 1] = ri;
            }
        }
        d_mag[o] = make_float2(sqrtf(lr * lr + li * li), sqrtf(rr * rr + ri * ri));
    }
}

// ---------------- persistent scan: all 19 steps, 2 batch rows per block ----------------
__global__ void __launch_bounds__(NTHR) k_steps(
        float* __restrict__ outYL, float* __restrict__ outYR, float* __restrict__ outQ,
        const float* __restrict__ w1, const float* __restrict__ b1,
        const float* __restrict__ g1, const float* __restrict__ be1,
        const float* __restrict__ w2, const float* __restrict__ b2,
        const float* __restrict__ g2, const float* __restrict__ be2,
        const float* __restrict__ w3, const float* __restrict__ b3) {
    extern __shared__ __align__(16) float dyn[];
    float* gpart = dyn;                                   // [KSPLIT][RPB*GC] (swizzled cols)
    float2 (*magc)[FFb] = (float2 (*)[FFb])dyn;           // [RPB][FFb] (aliased, R9 scheme)

    __shared__ __half2 a_h2[KTOT];             // GEMM input, (row0,row1) per k
    __shared__ float hold_s[RPB][128];         // fp32 h state
    __shared__ __align__(16) float hbuf[RPB][128];
    __shared__ __align__(16) float abuf[RPB][128];
    __shared__ float Qs[RPB][NBANDS];
    __shared__ float memLs[RPB][NBANDS], memRs[RPB][NBANDS];
    __shared__ float2 lnp[RPB][16];
    __shared__ float2 lnf[RPB];                // (mean, inv_std) broadcast

    int tid = threadIdx.x, lane = tid & 31, wid = tid >> 5;
    int b0 = blockIdx.x * RPB;
    __half* ah = (__half*)a_h2;

    // thread mapping for 4-way split-K phases
    int mrow = tid >> 9;                // 0..1
    int mo   = (tid >> 2) & 127;        // output index
    int mks  = tid & 3;                 // k-split lane

    // state init
    for (int i = tid; i < RPB*NBANDS; i += NTHR) {
        int r = i / NBANDS, n = i - r*NBANDS;
        Qs[r][n] = d_q0[n]; memLs[r][n] = 0.f; memRs[r][n] = 0.f;
    }
    if (tid < KTOT) a_h2[tid] = __floats2half2_rn(0.f, 0.f);
    if (tid < RPB*128) hold_s[tid >> 7][tid & 127] = 0.f;
    __syncthreads();

    for (int t = 0; t < TT; t++) {
        // ---- load magnitude rows ----
        for (int i = tid; i < RPB*FFb; i += NTHR) {
            int r = i / FFb, k = i - r*FFb;
            magc[r][k] = d_mag[(long long)((b0 + r)*TT + t)*FFb + k];
        }
        __syncthreads();

        // ---- gammatone filterbank: warp per (row,band), Gaussian recurrence ----
        for (int task = wid; task < RPB*NBANDS; task += 32) {
            int r = task / NBANDS, n = task - r*NBANDS;
            float Q  = Qs[r][n];
            float fc = d_fc[n];
            float bw = fc / (Q + 1e-8f) + 1e-8f;
            float inv = 1.0f / bw;
            float rad = 5.0f * bw;
            int kmin = (int)ceilf((fc - rad) * 0.064f);  if (kmin < 0)   kmin = 0;
            int kmax = (int)floorf((fc + rad) * 0.064f); if (kmax > 512) kmax = 512;
            float Dlt = 500.f * inv;                 // 32 bins * 15.625 Hz, in sigma units
            float c1 = __expf(-0.5f * Dlt * Dlt);
            float c2 = c1 * c1;
            int k = kmin + lane;
            float d0 = ((float)k * 15.625f - fc) * inv;
            float w  = __expf(-0.5f * d0 * d0);
            float u  = __expf(-d0 * Dlt);
            float sw = 0.f, sl = 0.f, sr = 0.f;
            for (; k <= kmax; k += 32) {
                float2 m = magc[r][k];
                sw += w; sl = fmaf(w, m.x, sl); sr = fmaf(w, m.y, sr);
                w = (w * c1) * u;
                u *= c2;
            }
#pragma unroll
            for (int off = 16; off; off >>= 1) {
                sw += __shfl_down_sync(0xffffffffu, sw, off);
                sl += __shfl_down_sync(0xffffffffu, sl, off);
                sr += __shfl_down_sync(0xffffffffu, sr, off);
            }
            if (lane == 0) {
                float den = 1.0f / (sw + 1e-8f);
                float yl = sl * den, yr = sr * den;
                long long oi = ((long long)(b0 + r)*TT + t)*NBANDS + n;
                outYL[oi] = yl; outYR[oi] = yr; outQ[oi] = Q;
                float cL = log1pf(fmaxf(yl, 0.f));
                float cR = log1pf(fmaxf(yr, 0.f));
                float mLo = memLs[r][n], mRo = memRs[r][n];
                ah[(n)*2       + r] = __float2half_rn(cL);
                ah[(100 + n)*2 + r] = __float2half_rn(mLo);
                ah[(200 + n)*2 + r] = __float2half_rn(cR);
                ah[(300 + n)*2 + r] = __float2half_rn(mRo);
                memLs[r][n] = 0.8f * mLo + 0.2f * cL;
                memRs[r][n] = 0.8f * mRo + 0.2f * cR;
            }
        }
        __syncthreads();   // filter done reading magc; gpart may clobber it

        // ---- GRU GEMM: warp = (colgroup, k16th); lane = 8 cols, both rows ----
        {
            int cg = wid >> 4, kq = wid & 15;
            int c0 = cg * 128 + lane * 4;                // half2 index
            __half2 acc0[4], acc1[4];
#pragma unroll
            for (int j = 0; j < 4; j++) {
                acc0[j] = __floats2half2_rn(0.f, 0.f);
                acc1[j] = __floats2half2_rn(0.f, 0.f);
            }
            int k0 = kq * 33;
            const uint4* wp = (const uint4*)(d_W2 + (size_t)k0*256 + c0);
            const __half2* ap = a_h2 + k0;
#pragma unroll 3
            for (int k = 0; k < 33; k++) {
                __half2 av = ap[k];
                __half2 a0 = __low2half2(av);
                __half2 a1 = __high2half2(av);
                uint4 w4 = wp[(size_t)k * 64];           // 256 half2 = 64 uint4 per k-row
                __half2 w0 = *(__half2*)&w4.x, w1h = *(__half2*)&w4.y;
                __half2 w2h = *(__half2*)&w4.z, w3h = *(__half2*)&w4.w;
                acc0[0] = __hfma2(w0, a0, acc0[0]);  acc1[0] = __hfma2(w0, a1, acc1[0]);
                acc0[1] = __hfma2(w1h, a0, acc0[1]); acc1[1] = __hfma2(w1h, a1, acc1[1]);
                acc0[2] = __hfma2(w2h, a0, acc0[2]); acc1[2] = __hfma2(w2h, a1, acc1[2]);
                acc0[3] = __hfma2(w3h, a0, acc0[3]); acc1[3] = __hfma2(w3h, a1, acc1[3]);
            }
            int cb = cg * 256 + lane * 8;
            int cw = (cb + kq * 8) & (GC - 1);           // swizzle (8-aligned)
            float* gp0 = gpart + kq*(RPB*GC) + cw;       // row0
            float* gp1 = gp0 + GC;                       // row1
            float2 f0 = __half22float2(acc0[0]), f1 = __half22float2(acc0[1]);
            float2 f2 = __half22float2(acc0[2]), f3 = __half22float2(acc0[3]);
            *(float4*)gp0       = make_float4(f0.x, f0.y, f1.x, f1.y);
            *(float4*)(gp0 + 4) = make_float4(f2.x, f2.y, f3.x, f3.y);
            f0 = __half22float2(acc1[0]); f1 = __half22float2(acc1[1]);
            f2 = __half22float2(acc1[2]); f3 = __half22float2(acc1[3]);
            *(float4*)gp1       = make_float4(f0.x, f0.y, f1.x, f1.y);
            *(float4*)(gp1 + 4) = make_float4(f2.x, f2.y, f3.x, f3.y);
        }
        __syncthreads();

        // ---- fused split-K reduce + GRU gating (all 1024 threads, 4-way) ----
        {
            int d = mo;
            float gr = 0.f, gz = 0.f, gin = 0.f, ghn = 0.f;
#pragma unroll
            for (int i = 0; i < 4; i++) {
                int q = mks + i * 4;
                const float* base = gpart + q*(RPB*GC) + mrow*GC;
                int sw8 = q * 8;
                gr  += base[(d       + sw8) & (GC-1)];
                gz  += base[(128 + d + sw8) & (GC-1)];
                gin += base[(256 + d + sw8) & (GC-1)];
                ghn += base[(384 + d + sw8) & (GC-1)];
            }
            gr  += __shfl_xor_sync(0xffffffffu, gr, 1);  gr  += __shfl_xor_sync(0xffffffffu, gr, 2);
            gz  += __shfl_xor_sync(0xffffffffu, gz, 1);  gz  += __shfl_xor_sync(0xffffffffu, gz, 2);
            gin += __shfl_xor_sync(0xffffffffu, gin, 1); gin += __shfl_xor_sync(0xffffffffu, gin, 2);
            ghn += __shfl_xor_sync(0xffffffffu, ghn, 1); ghn += __shfl_xor_sync(0xffffffffu, ghn, 2);
            if (mks == 0) {
                gr += d_biasc[d]; gz += d_biasc[128 + d];
                gin += d_biasc[256 + d]; ghn += d_biasc[384 + d];
                float rg = 1.f / (1.f + __expf(-gr));
                float zg = 1.f / (1.f + __expf(-gz));
                float ng = tanhf(gin + rg * ghn);
                float hn = (1.f - zg) * ng + zg * hold_s[mrow][d];
                hold_s[mrow][d] = hn;
                hbuf[mrow][d] = hn;
                ah[(400 + d)*2 + mrow] = __float2half_rn(hn);
            }
        }
        __syncthreads();

        // ---- MLP layer 1: v = hbuf @ w1^T (4-way split-K, all threads) ----
        float v1;
        {
            float acc = 0.f;
            const float* wr_ = w1 + mo*128 + mks*4;
#pragma unroll
            for (int j = 0; j < 8; j++) {
                float4 wv = *(const float4*)(wr_ + j*16);
                float4 hv = *(const float4*)&hbuf[mrow][j*16 + mks*4];
                acc += wv.x*hv.x + wv.y*hv.y + wv.z*hv.z + wv.w*hv.w;
            }
            acc += __shfl_xor_sync(0xffffffffu, acc, 1);
            acc += __shfl_xor_sync(0xffffffffu, acc, 2);
            v1 = acc + b1[mo];
            float s1 = v1, s2 = v1 * v1;
#pragma unroll
            for (int off = 16; off; off >>= 1) {
                s1 += __shfl_down_sync(0xffffffffu, s1, off);
                s2 += __shfl_down_sync(0xffffffffu, s2, off);
            }
            if (lane == 0) lnp[mrow][wid & 15] = make_float2(s1, s2);
        }
        __syncthreads();
        if (wid < RPB) {               // stage-2: warp w reduces row w
            float s1 = 0.f, s2 = 0.f;
            if (lane < 16) { float2 p = lnp[wid][lane]; s1 = p.x; s2 = p.y; }
#pragma unroll
            for (int off = 8; off; off >>= 1) {
                s1 += __shfl_down_sync(0xffffffffu, s1, off);
                s2 += __shfl_down_sync(0xffffffffu, s2, off);
            }
            if (lane == 0) {
                float mean = s1 * (1.f/512.f);
                float var  = s2 * (1.f/512.f) - mean * mean;
                lnf[wid] = make_float2(mean, rsqrtf(var + 1e-5f));
            }
        }
        __syncthreads();
        if (mks == 0) {
            float2 f = lnf[mrow];
            float x = (v1 - f.x) * f.y * g1[mo] + be1[mo];
            abuf[mrow][mo] = x / (1.f + __expf(-x));
        }
        __syncthreads();

        // ---- MLP layer 2 ----
        float v2;
        {
            float acc = 0.f;
            const float* wr_ = w2 + mo*128 + mks*4;
#pragma unroll
            for (int j = 0; j < 8; j++) {
                float4 wv = *(const float4*)(wr_ + j*16);
                float4 hv = *(const float4*)&abuf[mrow][j*16 + mks*4];
                acc += wv.x*hv.x + wv.y*hv.y + wv.z*hv.z + wv.w*hv.w;
            }
            acc += __shfl_xor_sync(0xffffffffu, acc, 1);
            acc += __shfl_xor_sync(0xffffffffu, acc, 2);
            v2 = acc + b2[mo];
            float s1 = v2, s2 = v2 * v2;
#pragma unroll
            for (int off = 16; off; off >>= 1) {
                s1 += __shfl_down_sync(0xffffffffu, s1, off);
                s2 += __shfl_down_sync(0xffffffffu, s2, off);
            }
            if (lane == 0) lnp[mrow][wid & 15] = make_float2(s1, s2);
        }
        __syncthreads();
        if (wid < RPB) {
            float s1 = 0.f, s2 = 0.f;
            if (lane < 16) { float2 p = lnp[wid][lane]; s1 = p.x; s2 = p.y; }
#pragma unroll
            for (int off = 8; off; off >>= 1) {
                s1 += __shfl_down_sync(0xffffffffu, s1, off);
                s2 += __shfl_down_sync(0xffffffffu, s2, off);
            }
            if (lane == 0) {
                float mean = s1 * (1.f/512.f);
                float var  = s2 * (1.f/512.f) - mean * mean;
                lnf[wid] = make_float2(mean, rsqrtf(var + 1e-5f));
            }
        }
        __syncthreads();
        if (mks == 0) {
            float2 f = lnf[mrow];
            float x = (v2 - f.x) * f.y * g2[mo] + be2[mo];
            hbuf[mrow][mo] = x / (1.f + __expf(-x));
        }
        __syncthreads();

        // ---- head + Q update: 800 threads, 4-way split-K ----
        if (tid < 800) {
            int row = tid / 400;
            int rem = tid - row * 400;
            int o = rem >> 2, ks = rem & 3;
            float acc = 0.f;
            const float* wr_ = w3 + o*128 + ks*4;
#pragma unroll
            for (int j = 0; j < 8; j++) {
                float4 wv = *(const float4*)(wr_ + j*16);
                float4 hv = *(const float4*)&hbuf[row][j*16 + ks*4];
                acc += wv.x*hv.x + wv.y*hv.y + wv.z*hv.z + wv.w*hv.w;
            }
            acc += __shfl_xor_sync(0xffffffffu, acc, 1);
            acc += __shfl_xor_sync(0xffffffffu, acc, 2);
            if (ks == 0) {
                float delta = tanhf(acc + b3[o]);
                float qt = d_q0[o] + delta * d_dq[o];
                float qn = 0.8f * Qs[row][o] + 0.2f * qt;
                Qs[row][o] = fminf(fmaxf(qn, 0.05f), 30.f);
            }
        }
        __syncthreads();
    }
}

// ---------------- launch ----------------
extern "C" void kernel_launch(void* const* d_in, const int* in_sizes, int n_in,
                              void* d_out, int out_size) {
    const float* wavL = (const float*)d_in[0];
    const float* wavR = (const float*)d_in[1];
    const float* w_ih = (const float*)d_in[2];
    const float* w_hh = (const float*)d_in[3];
    const float* b_ih = (const float*)d_in[4];
    const float* b_hh = (const float*)d_in[5];
    const float* w1  = (const float*)d_in[6];
    const float* b1  = (const float*)d_in[7];
    const float* g1  = (const float*)d_in[8];
    const float* be1 = (const float*)d_in[9];
    const float* w2  = (const float*)d_in[10];
    const float* b2  = (const float*)d_in[11];
    const float* g2  = (const float*)d_in[12];
    const float* be2 = (const float*)d_in[13];
    const float* w3  = (const float*)d_in[14];
    const float* b3  = (const float*)d_in[15];

    long long out_elems = (long long)out_size;
    const long long NYQ = 3LL * BB * TT * NBANDS;       // 1,459,200
    const long long XSZ = (long long)BB * TT * FFb;     // 2,495,232 per X (real plane)
    int realmode = (out_elems < NYQ + 3 * XSZ) ? 1 : 0;

    float* out = (float*)d_out;
    float* outYL = out;
    float* outYR = outYL + (long long)BB * TT * NBANDS;
    float* outQ  = outYR + (long long)BB * TT * NBANDS;
    long long xl_off = NYQ;
    long long xr_off = realmode ? (NYQ + XSZ) : (NYQ + 2 * XSZ);
    float* outXL = out + xl_off;
    float* outXR = out + xr_off;

    cudaFuncSetAttribute(k_steps, cudaFuncAttributeMaxDynamicSharedMemorySize, DYN_SMEM);

    const int PREP_N = KTOT*256 + GC;
    k_consts<<<1, 128>>>();
    k_prep<<<(PREP_N + 255) / 256, 256>>>(w_ih, w_hh, b_ih, b_hh);
    k_fft<<<BB * TT, 256>>>(wavL, wavR, outXL, outXR, realmode, xl_off, xr_off, out_elems);
    k_steps<<<NBLK, NTHR, DYN_SMEM>>>(outYL, outYR, outQ,
                                      w1, b1, g1, be1, w2, b2, g2, be2, w3, b3);
}